// round 1
// baseline (speedup 1.0000x reference)
#include <cuda_runtime.h>
#include <math.h>

#define N_TOK 4096
#define D_DIM 1024
#define E_NUM 8
#define F_DIM 4096
#define K_CAP 512

// -------- scratch (device globals; no allocations allowed) --------
__device__ float g_probT[E_NUM * N_TOK];            // [E, N] routing probs
__device__ int   g_routes[E_NUM * K_CAP];           // [E, k] token ids
__device__ float g_vals[E_NUM * K_CAP];             // [E, k] routing probs of chosen
__device__ float g_xin[(size_t)E_NUM * K_CAP * D_DIM];   // gathered inputs  16 MB
__device__ float g_h[(size_t)E_NUM * K_CAP * F_DIM];     // hidden acts      64 MB

// ---------------- zero output ----------------
__global__ void zero_out_kernel(float4* __restrict__ out) {
    out[blockIdx.x * blockDim.x + threadIdx.x] = make_float4(0.f, 0.f, 0.f, 0.f);
}

// ---------------- gating: logits -> softmax -> probT ----------------
// one warp per token; blockDim (32, 8)
__global__ void gating_kernel(const float* __restrict__ x,
                              const float* __restrict__ Ws,
                              const float* __restrict__ bs) {
    int t = blockIdx.x * 8 + threadIdx.y;
    int lane = threadIdx.x;
    const float* xr = x + (size_t)t * D_DIM;

    float acc[E_NUM];
#pragma unroll
    for (int e = 0; e < E_NUM; e++) acc[e] = 0.f;

    for (int i = lane; i < D_DIM; i += 32) {
        float xi = xr[i];
        const float* w = Ws + (size_t)i * E_NUM;
#pragma unroll
        for (int e = 0; e < E_NUM; e++) acc[e] += xi * w[e];
    }
#pragma unroll
    for (int e = 0; e < E_NUM; e++)
#pragma unroll
        for (int off = 16; off > 0; off >>= 1)
            acc[e] += __shfl_xor_sync(0xFFFFFFFFu, acc[e], off);

    if (lane == 0) {
        float mx = -1e30f;
#pragma unroll
        for (int e = 0; e < E_NUM; e++) { acc[e] += bs[e]; mx = fmaxf(mx, acc[e]); }
        float s = 0.f;
#pragma unroll
        for (int e = 0; e < E_NUM; e++) { acc[e] = __expf(acc[e] - mx); s += acc[e]; }
        float inv = 1.f / s;
#pragma unroll
        for (int e = 0; e < E_NUM; e++) g_probT[e * N_TOK + t] = acc[e] * inv;
    }
}

// ---------------- per-expert top-k via bitonic sort ----------------
// 8 blocks (one per expert), 512 threads, 4096 x 64-bit keys in smem.
// key = (float_bits << 32) | (~idx)  — probs >= 0 so uint compare == float compare.
// Sort ascending, take the top 512 from the tail. Order within top-k is
// irrelevant (final combine is a scatter-add); tie handling matches jax
// (equal values -> smaller index preferred, via the ~idx secondary key).
__global__ void topk_kernel() {
    __shared__ unsigned long long keys[N_TOK];  // 32 KB
    const int e = blockIdx.x;
    const int tid = threadIdx.x;

    for (int i = tid; i < N_TOK; i += 512) {
        unsigned vb = __float_as_uint(g_probT[e * N_TOK + i]);
        keys[i] = ((unsigned long long)vb << 32) | (unsigned)(0xFFFFFFFFu - (unsigned)i);
    }
    __syncthreads();

    for (int k = 2; k <= N_TOK; k <<= 1) {
        for (int j = k >> 1; j > 0; j >>= 1) {
            for (int i = tid; i < N_TOK; i += 512) {
                int ixj = i ^ j;
                if (ixj > i) {
                    unsigned long long a = keys[i], b = keys[ixj];
                    bool up = ((i & k) == 0);
                    if (up ? (a > b) : (a < b)) { keys[i] = b; keys[ixj] = a; }
                }
            }
            __syncthreads();
        }
    }

    for (int i = tid; i < K_CAP; i += 512) {
        unsigned long long kk = keys[N_TOK - K_CAP + i];
        g_vals[e * K_CAP + i]   = __uint_as_float((unsigned)(kk >> 32));
        g_routes[e * K_CAP + i] = (int)(0xFFFFFFFFu - (unsigned)(kk & 0xFFFFFFFFu));
    }
}

// ---------------- gather chosen token rows ----------------
__global__ void gather_kernel(const float* __restrict__ x) {
    int row = blockIdx.x;               // e*K_CAP + j
    int tok = g_routes[row];
    const float4* src = (const float4*)(x + (size_t)tok * D_DIM);
    float4* dst = (float4*)(g_xin + (size_t)row * D_DIM);
    dst[threadIdx.x] = src[threadIdx.x];   // 256 threads * 16B = 1024 floats
}

__device__ __forceinline__ float gelu_tanh(float v) {
    // matches jax.nn.gelu(approximate=True)
    float u = 0.7978845608028654f * (v + 0.044715f * v * v * v);
    return 0.5f * v * (1.0f + tanhf(u));
}

// ---------------- grouped GEMM, 128x128x8 tile, 256 threads, 8x8/thread ----
// EPI=0: C = gelu(g_xin[e] @ W1[e] + b1[e]) -> g_h      (K=1024, N=4096)
// EPI=1: scatter-add ( (g_h[e] @ W2[e] + b2[e]) * val ) (K=4096, N=1024)
template <int EPI>
__global__ __launch_bounds__(256, 2)
void moe_gemm(const float* __restrict__ Ball,
              const float* __restrict__ biasAll,
              float* __restrict__ outFinal) {
    constexpr int K  = (EPI == 0) ? D_DIM : F_DIM;
    constexpr int NC = (EPI == 0) ? F_DIM : D_DIM;

    const int e = blockIdx.z;
    const float* A    = (EPI == 0) ? (g_xin + (size_t)e * K_CAP * K)
                                   : (g_h   + (size_t)e * K_CAP * K);
    const float* B    = Ball   + (size_t)e * K * NC;
    const float* bias = biasAll + (size_t)e * NC;

    __shared__ float As[8][128];
    __shared__ float Bs[8][128];

    const int tid  = threadIdx.x;
    const int arow = tid >> 1, acol = (tid & 1) * 4;
    const int brow = tid >> 5, bcol = (tid & 31) * 4;

    const int m0 = blockIdx.y * 128;     // row tile
    const int n0 = blockIdx.x * 128;     // col tile

    const float* Aptr = A + (size_t)(m0 + arow) * K + acol;
    const float* Bptr = B + (size_t)brow * NC + n0 + bcol;

    const int tr = (tid >> 4) * 8;
    const int tc = (tid & 15) * 8;

    float acc[8][8];
#pragma unroll
    for (int i = 0; i < 8; i++)
#pragma unroll
        for (int j = 0; j < 8; j++) acc[i][j] = 0.f;

    for (int k0 = 0; k0 < K; k0 += 8) {
        float4 av = *(const float4*)Aptr;  Aptr += 8;
        float4 bv = *(const float4*)Bptr;  Bptr += (size_t)8 * NC;
        As[acol + 0][arow] = av.x;
        As[acol + 1][arow] = av.y;
        As[acol + 2][arow] = av.z;
        As[acol + 3][arow] = av.w;
        *(float4*)&Bs[brow][bcol] = bv;
        __syncthreads();

#pragma unroll
        for (int kk = 0; kk < 8; kk++) {
            float ra[8], rb[8];
            *(float4*)(ra)     = *(const float4*)&As[kk][tr];
            *(float4*)(ra + 4) = *(const float4*)&As[kk][tr + 4];
            *(float4*)(rb)     = *(const float4*)&Bs[kk][tc];
            *(float4*)(rb + 4) = *(const float4*)&Bs[kk][tc + 4];
#pragma unroll
            for (int i = 0; i < 8; i++)
#pragma unroll
                for (int j = 0; j < 8; j++) acc[i][j] += ra[i] * rb[j];
        }
        __syncthreads();
    }

    if (EPI == 0) {
#pragma unroll
        for (int i = 0; i < 8; i++) {
            const int m = m0 + tr + i;
            float* crow = g_h + ((size_t)e * K_CAP + m) * NC + n0 + tc;
#pragma unroll
            for (int j = 0; j < 8; j++) {
                float v = acc[i][j] + bias[n0 + tc + j];
                crow[j] = gelu_tanh(v);
            }
        }
    } else {
#pragma unroll
        for (int i = 0; i < 8; i++) {
            const int m = m0 + tr + i;
            const float scale = g_vals[e * K_CAP + m];
            const int tok = g_routes[e * K_CAP + m];
            float* orow = outFinal + (size_t)tok * D_DIM + n0 + tc;
#pragma unroll
            for (int j = 0; j < 8; j++) {
                float v = (acc[i][j] + bias[n0 + tc + j]) * scale;
                atomicAdd(&orow[j], v);
            }
        }
    }
}

extern "C" void kernel_launch(void* const* d_in, const int* in_sizes, int n_in,
                              void* d_out, int out_size) {
    const float* x  = (const float*)d_in[0];
    const float* Ws = (const float*)d_in[1];
    const float* bs = (const float*)d_in[2];
    const float* W1 = (const float*)d_in[3];
    const float* b1 = (const float*)d_in[4];
    const float* W2 = (const float*)d_in[5];
    const float* b2 = (const float*)d_in[6];
    float* out = (float*)d_out;

    zero_out_kernel<<<(N_TOK * D_DIM) / (256 * 4), 256>>>((float4*)out);
    gating_kernel<<<N_TOK / 8, dim3(32, 8)>>>(x, Ws, bs);
    topk_kernel<<<E_NUM, 512>>>();
    gather_kernel<<<E_NUM * K_CAP, 256>>>(x);
    moe_gemm<0><<<dim3(F_DIM / 128, K_CAP / 128, E_NUM), 256>>>(W1, b1, nullptr);
    moe_gemm<1><<<dim3(D_DIM / 128, K_CAP / 128, E_NUM), 256>>>(W2, b2, out);
}

// round 4
// speedup vs baseline: 2.1432x; 2.1432x over previous
#include <cuda_runtime.h>
#include <cuda_bf16.h>
#include <math.h>
#include <stdint.h>

#define N_TOK 4096
#define D_DIM 1024
#define E_NUM 8
#define F_DIM 4096
#define K_CAP 512

// -------- persistent scratch (device globals; no allocations allowed) --------
__device__ float g_probT[E_NUM * N_TOK];
__device__ int   g_routes[E_NUM * K_CAP];
__device__ float g_vals[E_NUM * K_CAP];
// split operands: hi/lo bf16
__device__ __align__(16) __nv_bfloat16 g_xh[(size_t)E_NUM * K_CAP * D_DIM];
__device__ __align__(16) __nv_bfloat16 g_xl[(size_t)E_NUM * K_CAP * D_DIM];
__device__ __align__(16) __nv_bfloat16 g_hh[(size_t)E_NUM * K_CAP * F_DIM];
__device__ __align__(16) __nv_bfloat16 g_hl[(size_t)E_NUM * K_CAP * F_DIM];
// weights transposed to [N][K], split
__device__ __align__(16) __nv_bfloat16 g_w1h[(size_t)E_NUM * F_DIM * D_DIM];
__device__ __align__(16) __nv_bfloat16 g_w1l[(size_t)E_NUM * F_DIM * D_DIM];
__device__ __align__(16) __nv_bfloat16 g_w2h[(size_t)E_NUM * D_DIM * F_DIM];
__device__ __align__(16) __nv_bfloat16 g_w2l[(size_t)E_NUM * D_DIM * F_DIM];

// ---------------- helpers ----------------
__device__ __forceinline__ uint32_t smem_u32(const void* p) {
    uint32_t a;
    asm("{ .reg .u64 t; cvta.to.shared.u64 t, %1; cvt.u32.u64 %0, t; }" : "=r"(a) : "l"(p));
    return a;
}
#define CP16(dst, src) \
    asm volatile("cp.async.cg.shared.global [%0], [%1], 16;" :: "r"(dst), "l"(src))
#define CP_COMMIT() asm volatile("cp.async.commit_group;" ::: "memory")
#define CP_WAIT0()  asm volatile("cp.async.wait_group 0;" ::: "memory")

__device__ __forceinline__ void mma16816(float* c, const uint32_t* a, const uint32_t* b) {
    asm volatile(
        "mma.sync.aligned.m16n8k16.row.col.f32.bf16.bf16.f32 "
        "{%0,%1,%2,%3}, {%4,%5,%6,%7}, {%8,%9}, {%0,%1,%2,%3};"
        : "+f"(c[0]), "+f"(c[1]), "+f"(c[2]), "+f"(c[3])
        : "r"(a[0]), "r"(a[1]), "r"(a[2]), "r"(a[3]), "r"(b[0]), "r"(b[1]));
}

__device__ __forceinline__ float gelu_tanh(float v) {
    float u = 0.7978845608028654f * (v + 0.044715f * v * v * v);
    return 0.5f * v * (1.0f + tanhf(u));
}
__device__ __forceinline__ uint32_t pack_bf2(float a, float b) {
    __nv_bfloat162 t = __floats2bfloat162_rn(a, b);
    return *(uint32_t*)&t;
}

// ---------------- zero output ----------------
__global__ void zero_out_kernel(float4* __restrict__ out) {
    out[blockIdx.x * blockDim.x + threadIdx.x] = make_float4(0.f, 0.f, 0.f, 0.f);
}

// ---------------- gating ----------------
__global__ void gating_kernel(const float* __restrict__ x,
                              const float* __restrict__ Ws,
                              const float* __restrict__ bs) {
    int t = blockIdx.x * 8 + threadIdx.y;
    int lane = threadIdx.x;
    const float* xr = x + (size_t)t * D_DIM;
    float acc[E_NUM];
#pragma unroll
    for (int e = 0; e < E_NUM; e++) acc[e] = 0.f;
    for (int i = lane; i < D_DIM; i += 32) {
        float xi = xr[i];
        const float* w = Ws + (size_t)i * E_NUM;
#pragma unroll
        for (int e = 0; e < E_NUM; e++) acc[e] += xi * w[e];
    }
#pragma unroll
    for (int e = 0; e < E_NUM; e++)
#pragma unroll
        for (int off = 16; off > 0; off >>= 1)
            acc[e] += __shfl_xor_sync(0xFFFFFFFFu, acc[e], off);
    if (lane == 0) {
        float mx = -1e30f;
#pragma unroll
        for (int e = 0; e < E_NUM; e++) { acc[e] += bs[e]; mx = fmaxf(mx, acc[e]); }
        float s = 0.f;
#pragma unroll
        for (int e = 0; e < E_NUM; e++) { acc[e] = __expf(acc[e] - mx); s += acc[e]; }
        float inv = 1.f / s;
#pragma unroll
        for (int e = 0; e < E_NUM; e++) g_probT[e * N_TOK + t] = acc[e] * inv;
    }
}

// ---------------- per-expert top-k (bitonic) ----------------
__global__ void topk_kernel() {
    __shared__ unsigned long long keys[N_TOK];
    const int e = blockIdx.x;
    const int tid = threadIdx.x;
    for (int i = tid; i < N_TOK; i += 512) {
        unsigned vb = __float_as_uint(g_probT[e * N_TOK + i]);
        keys[i] = ((unsigned long long)vb << 32) | (unsigned)(0xFFFFFFFFu - (unsigned)i);
    }
    __syncthreads();
    for (int k = 2; k <= N_TOK; k <<= 1) {
        for (int j = k >> 1; j > 0; j >>= 1) {
            for (int i = tid; i < N_TOK; i += 512) {
                int ixj = i ^ j;
                if (ixj > i) {
                    unsigned long long a = keys[i], b = keys[ixj];
                    bool up = ((i & k) == 0);
                    if (up ? (a > b) : (a < b)) { keys[i] = b; keys[ixj] = a; }
                }
            }
            __syncthreads();
        }
    }
    for (int i = tid; i < K_CAP; i += 512) {
        unsigned long long kk = keys[N_TOK - K_CAP + i];
        g_vals[e * K_CAP + i]   = __uint_as_float((unsigned)(kk >> 32));
        g_routes[e * K_CAP + i] = (int)(0xFFFFFFFFu - (unsigned)(kk & 0xFFFFFFFFu));
    }
}

// ---------------- gather + split ----------------
__global__ void gather_split_kernel(const float* __restrict__ x) {
    int row = blockIdx.x;                       // e*K_CAP + j
    int tok = g_routes[row];
    const float4* src = (const float4*)(x + (size_t)tok * D_DIM);
    float4 v = src[threadIdx.x];
    float hx = __bfloat162float(__float2bfloat16(v.x));
    float hy = __bfloat162float(__float2bfloat16(v.y));
    float hz = __bfloat162float(__float2bfloat16(v.z));
    float hw = __bfloat162float(__float2bfloat16(v.w));
    uint2 hi = make_uint2(pack_bf2(v.x, v.y), pack_bf2(v.z, v.w));
    uint2 lo = make_uint2(pack_bf2(v.x - hx, v.y - hy), pack_bf2(v.z - hz, v.w - hw));
    ((uint2*)(g_xh + (size_t)row * D_DIM))[threadIdx.x] = hi;
    ((uint2*)(g_xl + (size_t)row * D_DIM))[threadIdx.x] = lo;
}

// ---------------- weight transpose + split: src[R][C] -> dst[C][R] ----------------
template <int W>
__global__ void split_w(const float* __restrict__ src, int R, int C) {
    __shared__ float t[32][33];
    __nv_bfloat16* dh = W ? g_w2h : g_w1h;
    __nv_bfloat16* dl = W ? g_w2l : g_w1l;
    size_t mat = (size_t)blockIdx.z * R * C;
    int c0 = blockIdx.x * 32, r0 = blockIdx.y * 32;
#pragma unroll
    for (int j = threadIdx.y; j < 32; j += 8)
        t[j][threadIdx.x] = src[mat + (size_t)(r0 + j) * C + c0 + threadIdx.x];
    __syncthreads();
#pragma unroll
    for (int j = threadIdx.y; j < 32; j += 8) {
        float v = t[threadIdx.x][j];
        __nv_bfloat16 h = __float2bfloat16(v);
        size_t o = mat + (size_t)(c0 + j) * R + r0 + threadIdx.x;
        dh[o] = h;
        dl[o] = __float2bfloat16(v - __bfloat162float(h));
    }
}

// ---------------- bf16-split HMMA grouped GEMM ----------------
// CTA tile 128x128, BK=32, double-buffered cp.async.
// smem/stage: Ah(8K) Al(8K) Bh(8K) Bl(8K) = 32KB; 2 stages = 64KB.
// D = Ah@Bh + Al@Bh + Ah@Bl  (fp32 accum)
#define SMEM_BYTES (2 * 32768)

template <int EPI>
__global__ __launch_bounds__(256, 1)
void moe_mma(const float* __restrict__ biasAll, float* __restrict__ outFinal) {
    constexpr int K  = EPI ? F_DIM : D_DIM;
    constexpr int NC = EPI ? D_DIM : F_DIM;
    constexpr int ITERS = K / 32;

    extern __shared__ char sm[];
    const uint32_t sb = smem_u32(sm);

    const int tid = threadIdx.x, wid = tid >> 5, lane = tid & 31;
    const int gid = lane >> 2, tig = lane & 3;
    const int e = blockIdx.z, m0 = blockIdx.y * 128, n0 = blockIdx.x * 128;
    const int wm = (wid & 1) * 64, wn = (wid >> 1) * 32;

    const __nv_bfloat16* Agh = (EPI ? g_hh : g_xh) + (size_t)e * K_CAP * K;
    const __nv_bfloat16* Agl = (EPI ? g_hl : g_xl) + (size_t)e * K_CAP * K;
    const __nv_bfloat16* Bgh = (EPI ? g_w2h : g_w1h) + (size_t)e * (size_t)NC * K;
    const __nv_bfloat16* Bgl = (EPI ? g_w2l : g_w1l) + (size_t)e * (size_t)NC * K;

    float acc[4][4][4];
#pragma unroll
    for (int i = 0; i < 4; i++)
#pragma unroll
        for (int j = 0; j < 4; j++)
#pragma unroll
            for (int q = 0; q < 4; q++) acc[i][j][q] = 0.f;

    // producer: each thread moves 2 x 16B chunks per tensor per stage
    auto load_stage = [&](int stage, int k0) {
        const uint32_t base = sb + stage * 32768;
#pragma unroll
        for (int j = 0; j < 2; j++) {
            int cid = tid + j * 256;           // 0..511
            int row = cid >> 2, kb = cid & 3;  // row 0..127, 16B chunk 0..3
            int pk = kb ^ ((row >> 1) & 3);
            uint32_t doff = row * 64 + pk * 16;
            size_t aoff = (size_t)(m0 + row) * K + k0 + kb * 8;
            size_t boff = (size_t)(n0 + row) * K + k0 + kb * 8;
            CP16(base + doff,         Agh + aoff);
            CP16(base + 8192 + doff,  Agl + aoff);
            CP16(base + 16384 + doff, Bgh + boff);
            CP16(base + 24576 + doff, Bgl + boff);
        }
        CP_COMMIT();
    };

    load_stage(0, 0);

    int s = 0;
    for (int it = 0; it < ITERS; it++) {
        CP_WAIT0();
        __syncthreads();
        if (it + 1 < ITERS) load_stage(1 - s, (it + 1) * 32);

        const uint32_t* pAh = (const uint32_t*)(sm + s * 32768);
        const uint32_t* pAl = pAh + 2048;
        const uint32_t* pBh = pAh + 4096;
        const uint32_t* pBl = pAh + 6144;

#pragma unroll
        for (int sub = 0; sub < 2; sub++) {
            const int kp0 = sub * 8 + tig, kp1 = kp0 + 4;
            uint32_t ah[4][4], al[4][4], bh[4][2], bl[4][2];
#pragma unroll
            for (int mt = 0; mt < 4; mt++) {
                int r0 = wm + mt * 16 + gid, r1 = r0 + 8;
                int c0 = ((r0 >> 1) & 3) << 2, c1 = ((r1 >> 1) & 3) << 2;
                int i00 = r0 * 16 + (kp0 ^ c0), i10 = r1 * 16 + (kp0 ^ c1);
                int i01 = r0 * 16 + (kp1 ^ c0), i11 = r1 * 16 + (kp1 ^ c1);
                ah[mt][0] = pAh[i00]; ah[mt][1] = pAh[i10];
                ah[mt][2] = pAh[i01]; ah[mt][3] = pAh[i11];
                al[mt][0] = pAl[i00]; al[mt][1] = pAl[i10];
                al[mt][2] = pAl[i01]; al[mt][3] = pAl[i11];
            }
#pragma unroll
            for (int nt = 0; nt < 4; nt++) {
                int n = wn + nt * 8 + gid;
                int cn = ((n >> 1) & 3) << 2;
                int j0 = n * 16 + (kp0 ^ cn), j1 = n * 16 + (kp1 ^ cn);
                bh[nt][0] = pBh[j0]; bh[nt][1] = pBh[j1];
                bl[nt][0] = pBl[j0]; bl[nt][1] = pBl[j1];
            }
#pragma unroll
            for (int mt = 0; mt < 4; mt++)
#pragma unroll
                for (int nt = 0; nt < 4; nt++) {
                    mma16816(acc[mt][nt], ah[mt], bh[nt]);
                    mma16816(acc[mt][nt], al[mt], bh[nt]);
                    mma16816(acc[mt][nt], ah[mt], bl[nt]);
                }
        }
        s ^= 1;
    }

    // ---------------- epilogue ----------------
    const float* bias = biasAll + (size_t)e * NC;
    if (EPI == 0) {
#pragma unroll
        for (int mt = 0; mt < 4; mt++) {
#pragma unroll
            for (int half = 0; half < 2; half++) {
                int row = m0 + wm + mt * 16 + gid + half * 8;
                __nv_bfloat16* ph = g_hh + ((size_t)e * K_CAP + row) * F_DIM;
                __nv_bfloat16* pl = g_hl + ((size_t)e * K_CAP + row) * F_DIM;
#pragma unroll
                for (int nt = 0; nt < 4; nt++) {
                    int col = n0 + wn + nt * 8 + tig * 2;
                    float v0 = gelu_tanh(acc[mt][nt][half * 2 + 0] + bias[col]);
                    float v1 = gelu_tanh(acc[mt][nt][half * 2 + 1] + bias[col + 1]);
                    float h0 = __bfloat162float(__float2bfloat16(v0));
                    float h1 = __bfloat162float(__float2bfloat16(v1));
                    *(uint32_t*)(ph + col) = pack_bf2(v0, v1);
                    *(uint32_t*)(pl + col) = pack_bf2(v0 - h0, v1 - h1);
                }
            }
        }
    } else {
#pragma unroll
        for (int mt = 0; mt < 4; mt++) {
#pragma unroll
            for (int half = 0; half < 2; half++) {
                int row = m0 + wm + mt * 16 + gid + half * 8;
                const int tok = g_routes[e * K_CAP + row];
                const float scale = g_vals[e * K_CAP + row];
                float* orow = outFinal + (size_t)tok * D_DIM;
#pragma unroll
                for (int nt = 0; nt < 4; nt++) {
                    int col = n0 + wn + nt * 8 + tig * 2;
                    float v0 = (acc[mt][nt][half * 2 + 0] + bias[col]) * scale;
                    float v1 = (acc[mt][nt][half * 2 + 1] + bias[col + 1]) * scale;
                    atomicAdd(&orow[col], v0);
                    atomicAdd(&orow[col + 1], v1);
                }
            }
        }
    }
}

extern "C" void kernel_launch(void* const* d_in, const int* in_sizes, int n_in,
                              void* d_out, int out_size) {
    const float* x  = (const float*)d_in[0];
    const float* Ws = (const float*)d_in[1];
    const float* bs = (const float*)d_in[2];
    const float* W1 = (const float*)d_in[3];
    const float* b1 = (const float*)d_in[4];
    const float* W2 = (const float*)d_in[5];
    const float* b2 = (const float*)d_in[6];
    float* out = (float*)d_out;

    cudaFuncSetAttribute(moe_mma<0>, cudaFuncAttributeMaxDynamicSharedMemorySize, SMEM_BYTES);
    cudaFuncSetAttribute(moe_mma<1>, cudaFuncAttributeMaxDynamicSharedMemorySize, SMEM_BYTES);

    zero_out_kernel<<<(N_TOK * D_DIM) / (256 * 4), 256>>>((float4*)out);
    gating_kernel<<<N_TOK / 8, dim3(32, 8)>>>(x, Ws, bs);
    topk_kernel<<<E_NUM, 512>>>();
    gather_split_kernel<<<E_NUM * K_CAP, 256>>>(x);
    // W1 [D,F] -> [F,D] split;  W2 [F,D] -> [D,F] split
    split_w<0><<<dim3(F_DIM / 32, D_DIM / 32, E_NUM), dim3(32, 8)>>>(W1, D_DIM, F_DIM);
    split_w<1><<<dim3(D_DIM / 32, F_DIM / 32, E_NUM), dim3(32, 8)>>>(W2, F_DIM, D_DIM);
    moe_mma<0><<<dim3(F_DIM / 128, K_CAP / 128, E_NUM), 256, SMEM_BYTES>>>(b1, nullptr);
    moe_mma<1><<<dim3(D_DIM / 128, K_CAP / 128, E_NUM), 256, SMEM_BYTES>>>(b2, out);
}

// round 5
// speedup vs baseline: 2.2087x; 1.0306x over previous
#include <cuda_runtime.h>
#include <cuda_bf16.h>
#include <math.h>
#include <stdint.h>

#define N_TOK 4096
#define D_DIM 1024
#define E_NUM 8
#define F_DIM 4096
#define K_CAP 512

// -------- persistent scratch (device globals; no allocations allowed) --------
__device__ float g_probT[E_NUM * N_TOK];
__device__ int   g_routes[E_NUM * K_CAP];
__device__ float g_vals[E_NUM * K_CAP];
__device__ __align__(16) __nv_bfloat16 g_xh[(size_t)E_NUM * K_CAP * D_DIM];
__device__ __align__(16) __nv_bfloat16 g_xl[(size_t)E_NUM * K_CAP * D_DIM];
__device__ __align__(16) __nv_bfloat16 g_hh[(size_t)E_NUM * K_CAP * F_DIM];
__device__ __align__(16) __nv_bfloat16 g_hl[(size_t)E_NUM * K_CAP * F_DIM];
__device__ __align__(16) __nv_bfloat16 g_w1h[(size_t)E_NUM * F_DIM * D_DIM];
__device__ __align__(16) __nv_bfloat16 g_w1l[(size_t)E_NUM * F_DIM * D_DIM];
__device__ __align__(16) __nv_bfloat16 g_w2h[(size_t)E_NUM * D_DIM * F_DIM];
__device__ __align__(16) __nv_bfloat16 g_w2l[(size_t)E_NUM * D_DIM * F_DIM];

// ---------------- helpers ----------------
__device__ __forceinline__ uint32_t smem_u32(const void* p) {
    uint32_t a;
    asm("{ .reg .u64 t; cvta.to.shared.u64 t, %1; cvt.u32.u64 %0, t; }" : "=r"(a) : "l"(p));
    return a;
}
#define CP16(dst, src) \
    asm volatile("cp.async.cg.shared.global [%0], [%1], 16;" :: "r"(dst), "l"(src))
#define CP_COMMIT() asm volatile("cp.async.commit_group;" ::: "memory")
#define CP_WAIT0()  asm volatile("cp.async.wait_group 0;" ::: "memory")

__device__ __forceinline__ void mma16816(float* c, const uint32_t* a, const uint32_t* b) {
    asm volatile(
        "mma.sync.aligned.m16n8k16.row.col.f32.bf16.bf16.f32 "
        "{%0,%1,%2,%3}, {%4,%5,%6,%7}, {%8,%9}, {%0,%1,%2,%3};"
        : "+f"(c[0]), "+f"(c[1]), "+f"(c[2]), "+f"(c[3])
        : "r"(a[0]), "r"(a[1]), "r"(a[2]), "r"(a[3]), "r"(b[0]), "r"(b[1]));
}
__device__ __forceinline__ void ldsm4(uint32_t* d, uint32_t addr) {
    asm volatile("ldmatrix.sync.aligned.m8n8.x4.shared.b16 {%0,%1,%2,%3}, [%4];"
                 : "=r"(d[0]), "=r"(d[1]), "=r"(d[2]), "=r"(d[3]) : "r"(addr));
}
__device__ __forceinline__ float gelu_tanh(float v) {
    float u = 0.7978845608028654f * (v + 0.044715f * v * v * v);
    float t;
    asm("tanh.approx.f32 %0, %1;" : "=f"(t) : "f"(u));
    return 0.5f * v * (1.0f + t);
}
__device__ __forceinline__ uint32_t pack_bf2(float a, float b) {
    __nv_bfloat162 t = __floats2bfloat162_rn(a, b);
    return *(uint32_t*)&t;
}

// ---------------- zero output ----------------
__global__ void zero_out_kernel(float4* __restrict__ out) {
    out[blockIdx.x * blockDim.x + threadIdx.x] = make_float4(0.f, 0.f, 0.f, 0.f);
}

// ---------------- gating ----------------
__global__ void gating_kernel(const float* __restrict__ x,
                              const float* __restrict__ Ws,
                              const float* __restrict__ bs) {
    int t = blockIdx.x * 8 + threadIdx.y;
    int lane = threadIdx.x;
    const float* xr = x + (size_t)t * D_DIM;
    float acc[E_NUM];
#pragma unroll
    for (int e = 0; e < E_NUM; e++) acc[e] = 0.f;
    for (int i = lane; i < D_DIM; i += 32) {
        float xi = xr[i];
        const float* w = Ws + (size_t)i * E_NUM;
#pragma unroll
        for (int e = 0; e < E_NUM; e++) acc[e] += xi * w[e];
    }
#pragma unroll
    for (int e = 0; e < E_NUM; e++)
#pragma unroll
        for (int off = 16; off > 0; off >>= 1)
            acc[e] += __shfl_xor_sync(0xFFFFFFFFu, acc[e], off);
    if (lane == 0) {
        float mx = -1e30f;
#pragma unroll
        for (int e = 0; e < E_NUM; e++) { acc[e] += bs[e]; mx = fmaxf(mx, acc[e]); }
        float s = 0.f;
#pragma unroll
        for (int e = 0; e < E_NUM; e++) { acc[e] = __expf(acc[e] - mx); s += acc[e]; }
        float inv = 1.f / s;
#pragma unroll
        for (int e = 0; e < E_NUM; e++) g_probT[e * N_TOK + t] = acc[e] * inv;
    }
}

// ---------------- per-expert top-k (bitonic) ----------------
__global__ void topk_kernel() {
    __shared__ unsigned long long keys[N_TOK];
    const int e = blockIdx.x;
    const int tid = threadIdx.x;
    for (int i = tid; i < N_TOK; i += 512) {
        unsigned vb = __float_as_uint(g_probT[e * N_TOK + i]);
        keys[i] = ((unsigned long long)vb << 32) | (unsigned)(0xFFFFFFFFu - (unsigned)i);
    }
    __syncthreads();
    for (int k = 2; k <= N_TOK; k <<= 1) {
        for (int j = k >> 1; j > 0; j >>= 1) {
            for (int i = tid; i < N_TOK; i += 512) {
                int ixj = i ^ j;
                if (ixj > i) {
                    unsigned long long a = keys[i], b = keys[ixj];
                    bool up = ((i & k) == 0);
                    if (up ? (a > b) : (a < b)) { keys[i] = b; keys[ixj] = a; }
                }
            }
            __syncthreads();
        }
    }
    for (int i = tid; i < K_CAP; i += 512) {
        unsigned long long kk = keys[N_TOK - K_CAP + i];
        g_vals[e * K_CAP + i]   = __uint_as_float((unsigned)(kk >> 32));
        g_routes[e * K_CAP + i] = (int)(0xFFFFFFFFu - (unsigned)(kk & 0xFFFFFFFFu));
    }
}

// ---------------- gather + split ----------------
__global__ void gather_split_kernel(const float* __restrict__ x) {
    int row = blockIdx.x;
    int tok = g_routes[row];
    const float4* src = (const float4*)(x + (size_t)tok * D_DIM);
    float4 v = src[threadIdx.x];
    float hx = __bfloat162float(__float2bfloat16(v.x));
    float hy = __bfloat162float(__float2bfloat16(v.y));
    float hz = __bfloat162float(__float2bfloat16(v.z));
    float hw = __bfloat162float(__float2bfloat16(v.w));
    uint2 hi = make_uint2(pack_bf2(v.x, v.y), pack_bf2(v.z, v.w));
    uint2 lo = make_uint2(pack_bf2(v.x - hx, v.y - hy), pack_bf2(v.z - hz, v.w - hw));
    ((uint2*)(g_xh + (size_t)row * D_DIM))[threadIdx.x] = hi;
    ((uint2*)(g_xl + (size_t)row * D_DIM))[threadIdx.x] = lo;
}

// ---------------- weight transpose + split ----------------
template <int W>
__global__ void split_w(const float* __restrict__ src, int R, int C) {
    __shared__ float t[32][33];
    __nv_bfloat16* dh = W ? g_w2h : g_w1h;
    __nv_bfloat16* dl = W ? g_w2l : g_w1l;
    size_t mat = (size_t)blockIdx.z * R * C;
    int c0 = blockIdx.x * 32, r0 = blockIdx.y * 32;
#pragma unroll
    for (int j = threadIdx.y; j < 32; j += 8)
        t[j][threadIdx.x] = src[mat + (size_t)(r0 + j) * C + c0 + threadIdx.x];
    __syncthreads();
#pragma unroll
    for (int j = threadIdx.y; j < 32; j += 8) {
        float v = t[threadIdx.x][j];
        __nv_bfloat16 h = __float2bfloat16(v);
        size_t o = mat + (size_t)(c0 + j) * R + r0 + threadIdx.x;
        dh[o] = h;
        dl[o] = __float2bfloat16(v - __bfloat162float(h));
    }
}

// ---------------- bf16-split HMMA grouped GEMM ----------------
// CTA tile 128x128, BK=32, double-buffered cp.async, ldmatrix fragment loads.
// D = Ah@Bh + Al@Bh + Ah@Bl  (fp32 accum)
#define SMEM_BYTES (2 * 32768)

template <int EPI>
__global__ __launch_bounds__(256, 1)
void moe_mma(const float* __restrict__ biasAll, float* __restrict__ outFinal) {
    constexpr int K  = EPI ? F_DIM : D_DIM;
    constexpr int NC = EPI ? D_DIM : F_DIM;
    constexpr int ITERS = K / 32;

    extern __shared__ char sm[];
    const uint32_t sb = smem_u32(sm);

    const int tid = threadIdx.x, wid = tid >> 5, lane = tid & 31;
    const int e = blockIdx.z, m0 = blockIdx.y * 128, n0 = blockIdx.x * 128;
    const int wm = (wid & 1) * 64, wn = (wid >> 1) * 32;

    const __nv_bfloat16* Agh = (EPI ? g_hh : g_xh) + (size_t)e * K_CAP * K;
    const __nv_bfloat16* Agl = (EPI ? g_hl : g_xl) + (size_t)e * K_CAP * K;
    const __nv_bfloat16* Bgh = (EPI ? g_w2h : g_w1h) + (size_t)e * (size_t)NC * K;
    const __nv_bfloat16* Bgl = (EPI ? g_w2l : g_w1l) + (size_t)e * (size_t)NC * K;

    // ldmatrix per-lane address precomputation.
    // smem tile layout: 128 rows x 64B (16 u32); chunk(row,kb) at row*64 + ((kb^((row>>1)&3))<<4)
    const int mi = lane >> 3, j = lane & 7;
    // A: matrices {rows r0..+7 kb0 | rows r0+8.. kb0 | r0.. kb0+1 | r0+8.. kb0+1}
    uint32_t a_rowterm[4], a_xr[4];
    const int a_kbh = mi >> 1;                 // chunk half selector
#pragma unroll
    for (int mt = 0; mt < 4; mt++) {
        int row = wm + mt * 16 + ((mi & 1) << 3) + j;
        a_rowterm[mt] = row * 64;
        a_xr[mt] = (row >> 1) & 3;
    }
    // B: matrices {rows nb..+7 kb0 | nb.. kb0+1 | nb+8.. kb0 | nb+8.. kb0+1}
    uint32_t b_rowterm[2], b_xr[2];
    const int b_kbh = mi & 1;
#pragma unroll
    for (int ntp = 0; ntp < 2; ntp++) {
        int row = wn + ntp * 16 + ((mi >> 1) << 3) + j;
        b_rowterm[ntp] = row * 64;
        b_xr[ntp] = (row >> 1) & 3;
    }

    float acc[4][4][4];
#pragma unroll
    for (int i = 0; i < 4; i++)
#pragma unroll
        for (int jj = 0; jj < 4; jj++)
#pragma unroll
            for (int q = 0; q < 4; q++) acc[i][jj][q] = 0.f;

    auto load_stage = [&](int stage, int k0) {
        const uint32_t base = sb + stage * 32768;
#pragma unroll
        for (int jj = 0; jj < 2; jj++) {
            int cid = tid + jj * 256;
            int row = cid >> 2, kb = cid & 3;
            int pk = kb ^ ((row >> 1) & 3);
            uint32_t doff = row * 64 + pk * 16;
            size_t aoff = (size_t)(m0 + row) * K + k0 + kb * 8;
            size_t boff = (size_t)(n0 + row) * K + k0 + kb * 8;
            CP16(base + doff,         Agh + aoff);
            CP16(base + 8192 + doff,  Agl + aoff);
            CP16(base + 16384 + doff, Bgh + boff);
            CP16(base + 24576 + doff, Bgl + boff);
        }
        CP_COMMIT();
    };

    load_stage(0, 0);

    int s = 0;
    for (int it = 0; it < ITERS; it++) {
        CP_WAIT0();
        __syncthreads();
        if (it + 1 < ITERS) load_stage(1 - s, (it + 1) * 32);

        const uint32_t baseAh = sb + s * 32768;
        const uint32_t baseAl = baseAh + 8192;
        const uint32_t baseBh = baseAh + 16384;
        const uint32_t baseBl = baseAh + 24576;

#pragma unroll
        for (int sub = 0; sub < 2; sub++) {
            uint32_t ah[4][4], al[4][4], bf_h[2][4], bf_l[2][4];
#pragma unroll
            for (int mt = 0; mt < 4; mt++) {
                uint32_t off = a_rowterm[mt] + ((((uint32_t)(2 * sub + a_kbh)) ^ a_xr[mt]) << 4);
                ldsm4(ah[mt], baseAh + off);
                ldsm4(al[mt], baseAl + off);
            }
#pragma unroll
            for (int ntp = 0; ntp < 2; ntp++) {
                uint32_t off = b_rowterm[ntp] + ((((uint32_t)(2 * sub + b_kbh)) ^ b_xr[ntp]) << 4);
                ldsm4(bf_h[ntp], baseBh + off);
                ldsm4(bf_l[ntp], baseBl + off);
            }
            // bf_h[ntp] = {b(2ntp)[0], b(2ntp)[1], b(2ntp+1)[0], b(2ntp+1)[1]}
#pragma unroll
            for (int mt = 0; mt < 4; mt++)
#pragma unroll
                for (int nt = 0; nt < 4; nt++) {
                    const uint32_t* bh2 = &bf_h[nt >> 1][(nt & 1) * 2];
                    const uint32_t* bl2 = &bf_l[nt >> 1][(nt & 1) * 2];
                    mma16816(acc[mt][nt], ah[mt], bh2);
                    mma16816(acc[mt][nt], al[mt], bh2);
                    mma16816(acc[mt][nt], ah[mt], bl2);
                }
        }
        s ^= 1;
    }

    // ---------------- epilogue ----------------
    const int gid = lane >> 2, tig = lane & 3;
    const float* bias = biasAll + (size_t)e * NC;
    if (EPI == 0) {
#pragma unroll
        for (int mt = 0; mt < 4; mt++) {
#pragma unroll
            for (int half = 0; half < 2; half++) {
                int row = m0 + wm + mt * 16 + gid + half * 8;
                __nv_bfloat16* ph = g_hh + ((size_t)e * K_CAP + row) * F_DIM;
                __nv_bfloat16* pl = g_hl + ((size_t)e * K_CAP + row) * F_DIM;
#pragma unroll
                for (int nt = 0; nt < 4; nt++) {
                    int col = n0 + wn + nt * 8 + tig * 2;
                    float v0 = gelu_tanh(acc[mt][nt][half * 2 + 0] + bias[col]);
                    float v1 = gelu_tanh(acc[mt][nt][half * 2 + 1] + bias[col + 1]);
                    float h0 = __bfloat162float(__float2bfloat16(v0));
                    float h1 = __bfloat162float(__float2bfloat16(v1));
                    *(uint32_t*)(ph + col) = pack_bf2(v0, v1);
                    *(uint32_t*)(pl + col) = pack_bf2(v0 - h0, v1 - h1);
                }
            }
        }
    } else {
#pragma unroll
        for (int mt = 0; mt < 4; mt++) {
#pragma unroll
            for (int half = 0; half < 2; half++) {
                int row = m0 + wm + mt * 16 + gid + half * 8;
                const int tok = g_routes[e * K_CAP + row];
                const float scale = g_vals[e * K_CAP + row];
                float* orow = outFinal + (size_t)tok * D_DIM;
#pragma unroll
                for (int nt = 0; nt < 4; nt++) {
                    int col = n0 + wn + nt * 8 + tig * 2;
                    float v0 = (acc[mt][nt][half * 2 + 0] + bias[col]) * scale;
                    float v1 = (acc[mt][nt][half * 2 + 1] + bias[col + 1]) * scale;
                    atomicAdd(&orow[col], v0);
                    atomicAdd(&orow[col + 1], v1);
                }
            }
        }
    }
}

extern "C" void kernel_launch(void* const* d_in, const int* in_sizes, int n_in,
                              void* d_out, int out_size) {
    const float* x  = (const float*)d_in[0];
    const float* Ws = (const float*)d_in[1];
    const float* bs = (const float*)d_in[2];
    const float* W1 = (const float*)d_in[3];
    const float* b1 = (const float*)d_in[4];
    const float* W2 = (const float*)d_in[5];
    const float* b2 = (const float*)d_in[6];
    float* out = (float*)d_out;

    cudaFuncSetAttribute(moe_mma<0>, cudaFuncAttributeMaxDynamicSharedMemorySize, SMEM_BYTES);
    cudaFuncSetAttribute(moe_mma<1>, cudaFuncAttributeMaxDynamicSharedMemorySize, SMEM_BYTES);

    zero_out_kernel<<<(N_TOK * D_DIM) / (256 * 4), 256>>>((float4*)out);
    gating_kernel<<<N_TOK / 8, dim3(32, 8)>>>(x, Ws, bs);
    topk_kernel<<<E_NUM, 512>>>();
    gather_split_kernel<<<E_NUM * K_CAP, 256>>>(x);
    split_w<0><<<dim3(F_DIM / 32, D_DIM / 32, E_NUM), dim3(32, 8)>>>(W1, D_DIM, F_DIM);
    split_w<1><<<dim3(D_DIM / 32, F_DIM / 32, E_NUM), dim3(32, 8)>>>(W2, F_DIM, D_DIM);
    moe_mma<0><<<dim3(F_DIM / 128, K_CAP / 128, E_NUM), 256, SMEM_BYTES>>>(b1, nullptr);
    moe_mma<1><<<dim3(D_DIM / 128, K_CAP / 128, E_NUM), 256, SMEM_BYTES>>>(b2, out);
}

// round 6
// speedup vs baseline: 2.3931x; 1.0835x over previous
#include <cuda_runtime.h>
#include <cuda_bf16.h>
#include <math.h>
#include <stdint.h>

#define N_TOK 4096
#define D_DIM 1024
#define E_NUM 8
#define F_DIM 4096
#define K_CAP 512

// -------- persistent scratch (device globals; no allocations allowed) --------
__device__ float g_probT[E_NUM * N_TOK];
__device__ int   g_routes[E_NUM * K_CAP];
__device__ float g_vals[E_NUM * K_CAP];
__device__ __align__(16) __nv_bfloat16 g_xh[(size_t)E_NUM * K_CAP * D_DIM];
__device__ __align__(16) __nv_bfloat16 g_xl[(size_t)E_NUM * K_CAP * D_DIM];
__device__ __align__(16) __nv_bfloat16 g_hh[(size_t)E_NUM * K_CAP * F_DIM];
__device__ __align__(16) __nv_bfloat16 g_hl[(size_t)E_NUM * K_CAP * F_DIM];
__device__ __align__(16) __nv_bfloat16 g_w1h[(size_t)E_NUM * F_DIM * D_DIM];
__device__ __align__(16) __nv_bfloat16 g_w1l[(size_t)E_NUM * F_DIM * D_DIM];
__device__ __align__(16) __nv_bfloat16 g_w2h[(size_t)E_NUM * D_DIM * F_DIM];
__device__ __align__(16) __nv_bfloat16 g_w2l[(size_t)E_NUM * D_DIM * F_DIM];

// ---------------- helpers ----------------
__device__ __forceinline__ uint32_t smem_u32(const void* p) {
    uint32_t a;
    asm("{ .reg .u64 t; cvta.to.shared.u64 t, %1; cvt.u32.u64 %0, t; }" : "=r"(a) : "l"(p));
    return a;
}
#define CP16(dst, src) \
    asm volatile("cp.async.cg.shared.global [%0], [%1], 16;" :: "r"(dst), "l"(src))
#define CP_COMMIT() asm volatile("cp.async.commit_group;" ::: "memory")
#define CP_WAIT(n)  asm volatile("cp.async.wait_group %0;" :: "n"(n) : "memory")

__device__ __forceinline__ void mma16816(float* c, const uint32_t* a, const uint32_t* b) {
    asm volatile(
        "mma.sync.aligned.m16n8k16.row.col.f32.bf16.bf16.f32 "
        "{%0,%1,%2,%3}, {%4,%5,%6,%7}, {%8,%9}, {%0,%1,%2,%3};"
        : "+f"(c[0]), "+f"(c[1]), "+f"(c[2]), "+f"(c[3])
        : "r"(a[0]), "r"(a[1]), "r"(a[2]), "r"(a[3]), "r"(b[0]), "r"(b[1]));
}
__device__ __forceinline__ void ldsm4(uint32_t* d, uint32_t addr) {
    asm volatile("ldmatrix.sync.aligned.m8n8.x4.shared.b16 {%0,%1,%2,%3}, [%4];"
                 : "=r"(d[0]), "=r"(d[1]), "=r"(d[2]), "=r"(d[3]) : "r"(addr));
}
__device__ __forceinline__ float gelu_tanh(float v) {
    float u = 0.7978845608028654f * (v + 0.044715f * v * v * v);
    float t;
    asm("tanh.approx.f32 %0, %1;" : "=f"(t) : "f"(u));
    return 0.5f * v * (1.0f + t);
}
__device__ __forceinline__ uint32_t pack_bf2(float a, float b) {
    __nv_bfloat162 t = __floats2bfloat162_rn(a, b);
    return *(uint32_t*)&t;
}

// ---------------- zero output ----------------
__global__ void zero_out_kernel(float4* __restrict__ out) {
    out[blockIdx.x * blockDim.x + threadIdx.x] = make_float4(0.f, 0.f, 0.f, 0.f);
}

// ---------------- gating ----------------
__global__ void gating_kernel(const float* __restrict__ x,
                              const float* __restrict__ Ws,
                              const float* __restrict__ bs) {
    int t = blockIdx.x * 8 + threadIdx.y;
    int lane = threadIdx.x;
    const float* xr = x + (size_t)t * D_DIM;
    float acc[E_NUM];
#pragma unroll
    for (int e = 0; e < E_NUM; e++) acc[e] = 0.f;
    for (int i = lane; i < D_DIM; i += 32) {
        float xi = xr[i];
        const float* w = Ws + (size_t)i * E_NUM;
#pragma unroll
        for (int e = 0; e < E_NUM; e++) acc[e] += xi * w[e];
    }
#pragma unroll
    for (int e = 0; e < E_NUM; e++)
#pragma unroll
        for (int off = 16; off > 0; off >>= 1)
            acc[e] += __shfl_xor_sync(0xFFFFFFFFu, acc[e], off);
    if (lane == 0) {
        float mx = -1e30f;
#pragma unroll
        for (int e = 0; e < E_NUM; e++) { acc[e] += bs[e]; mx = fmaxf(mx, acc[e]); }
        float s = 0.f;
#pragma unroll
        for (int e = 0; e < E_NUM; e++) { acc[e] = __expf(acc[e] - mx); s += acc[e]; }
        float inv = 1.f / s;
#pragma unroll
        for (int e = 0; e < E_NUM; e++) g_probT[e * N_TOK + t] = acc[e] * inv;
    }
}

// ---------------- per-expert top-k (bitonic) ----------------
__global__ void topk_kernel() {
    __shared__ unsigned long long keys[N_TOK];
    const int e = blockIdx.x;
    const int tid = threadIdx.x;
    for (int i = tid; i < N_TOK; i += 512) {
        unsigned vb = __float_as_uint(g_probT[e * N_TOK + i]);
        keys[i] = ((unsigned long long)vb << 32) | (unsigned)(0xFFFFFFFFu - (unsigned)i);
    }
    __syncthreads();
    for (int k = 2; k <= N_TOK; k <<= 1) {
        for (int j = k >> 1; j > 0; j >>= 1) {
            for (int i = tid; i < N_TOK; i += 512) {
                int ixj = i ^ j;
                if (ixj > i) {
                    unsigned long long a = keys[i], b = keys[ixj];
                    bool up = ((i & k) == 0);
                    if (up ? (a > b) : (a < b)) { keys[i] = b; keys[ixj] = a; }
                }
            }
            __syncthreads();
        }
    }
    for (int i = tid; i < K_CAP; i += 512) {
        unsigned long long kk = keys[N_TOK - K_CAP + i];
        g_vals[e * K_CAP + i]   = __uint_as_float((unsigned)(kk >> 32));
        g_routes[e * K_CAP + i] = (int)(0xFFFFFFFFu - (unsigned)(kk & 0xFFFFFFFFu));
    }
}

// ---------------- gather + split ----------------
__global__ void gather_split_kernel(const float* __restrict__ x) {
    int row = blockIdx.x;
    int tok = g_routes[row];
    const float4* src = (const float4*)(x + (size_t)tok * D_DIM);
    float4 v = src[threadIdx.x];
    float hx = __bfloat162float(__float2bfloat16(v.x));
    float hy = __bfloat162float(__float2bfloat16(v.y));
    float hz = __bfloat162float(__float2bfloat16(v.z));
    float hw = __bfloat162float(__float2bfloat16(v.w));
    uint2 hi = make_uint2(pack_bf2(v.x, v.y), pack_bf2(v.z, v.w));
    uint2 lo = make_uint2(pack_bf2(v.x - hx, v.y - hy), pack_bf2(v.z - hz, v.w - hw));
    ((uint2*)(g_xh + (size_t)row * D_DIM))[threadIdx.x] = hi;
    ((uint2*)(g_xl + (size_t)row * D_DIM))[threadIdx.x] = lo;
}

// ---------------- weight transpose + split ----------------
template <int W>
__global__ void split_w(const float* __restrict__ src, int R, int C) {
    __shared__ float t[32][33];
    __nv_bfloat16* dh = W ? g_w2h : g_w1h;
    __nv_bfloat16* dl = W ? g_w2l : g_w1l;
    size_t mat = (size_t)blockIdx.z * R * C;
    int c0 = blockIdx.x * 32, r0 = blockIdx.y * 32;
#pragma unroll
    for (int j = threadIdx.y; j < 32; j += 8)
        t[j][threadIdx.x] = src[mat + (size_t)(r0 + j) * C + c0 + threadIdx.x];
    __syncthreads();
#pragma unroll
    for (int j = threadIdx.y; j < 32; j += 8) {
        float v = t[threadIdx.x][j];
        __nv_bfloat16 h = __float2bfloat16(v);
        size_t o = mat + (size_t)(c0 + j) * R + r0 + threadIdx.x;
        dh[o] = h;
        dl[o] = __float2bfloat16(v - __bfloat162float(h));
    }
}

// ---------------- bf16-split HMMA grouped GEMM ----------------
// CTA tile 128x128, BK=32, 3-stage cp.async ring (wait_group 1), occupancy 2.
// D = Ah@Bh + Al@Bh + Ah@Bl  (fp32 accum)
#define STAGE_BYTES 32768
#define SMEM_BYTES (3 * STAGE_BYTES)

template <int EPI>
__global__ __launch_bounds__(256, 2)
void moe_mma(const float* __restrict__ biasAll, float* __restrict__ outFinal) {
    constexpr int K  = EPI ? F_DIM : D_DIM;
    constexpr int NC = EPI ? D_DIM : F_DIM;
    constexpr int ITERS = K / 32;

    extern __shared__ char sm[];
    const uint32_t sb = smem_u32(sm);

    const int tid = threadIdx.x, wid = tid >> 5, lane = tid & 31;
    const int e = blockIdx.z, m0 = blockIdx.y * 128, n0 = blockIdx.x * 128;
    const int wm = (wid & 1) * 64, wn = (wid >> 1) * 32;

    const __nv_bfloat16* Agh = (EPI ? g_hh : g_xh) + (size_t)e * K_CAP * K;
    const __nv_bfloat16* Agl = (EPI ? g_hl : g_xl) + (size_t)e * K_CAP * K;
    const __nv_bfloat16* Bgh = (EPI ? g_w2h : g_w1h) + (size_t)e * (size_t)NC * K;
    const __nv_bfloat16* Bgl = (EPI ? g_w2l : g_w1l) + (size_t)e * (size_t)NC * K;

    // ldmatrix per-lane address precomputation (layout identical to round 5).
    const int mi = lane >> 3, j = lane & 7;
    uint32_t a_rowterm[4], a_xr[4];
    const int a_kbh = mi >> 1;
#pragma unroll
    for (int mt = 0; mt < 4; mt++) {
        int row = wm + mt * 16 + ((mi & 1) << 3) + j;
        a_rowterm[mt] = row * 64;
        a_xr[mt] = (row >> 1) & 3;
    }
    uint32_t b_rowterm[2], b_xr[2];
    const int b_kbh = mi & 1;
#pragma unroll
    for (int ntp = 0; ntp < 2; ntp++) {
        int row = wn + ntp * 16 + ((mi >> 1) << 3) + j;
        b_rowterm[ntp] = row * 64;
        b_xr[ntp] = (row >> 1) & 3;
    }

    float acc[4][4][4];
#pragma unroll
    for (int i = 0; i < 4; i++)
#pragma unroll
        for (int jj = 0; jj < 4; jj++)
#pragma unroll
            for (int q = 0; q < 4; q++) acc[i][jj][q] = 0.f;

    // producer: each thread moves 2 x 16B chunks per tensor per stage
    const int p_row = tid >> 1;                  // pair rows: tid covers 128 rows x 2 chunks... see below
    auto load_stage = [&](int stage, int k0) {
        const uint32_t base = sb + stage * STAGE_BYTES;
#pragma unroll
        for (int jj = 0; jj < 2; jj++) {
            int cid = tid + jj * 256;
            int row = cid >> 2, kb = cid & 3;
            int pk = kb ^ ((row >> 1) & 3);
            uint32_t doff = row * 64 + pk * 16;
            size_t aoff = (size_t)(m0 + row) * K + k0 + kb * 8;
            size_t boff = (size_t)(n0 + row) * K + k0 + kb * 8;
            CP16(base + doff,         Agh + aoff);
            CP16(base + 8192 + doff,  Agl + aoff);
            CP16(base + 16384 + doff, Bgh + boff);
            CP16(base + 24576 + doff, Bgl + boff);
        }
        CP_COMMIT();
    };

    load_stage(0, 0);
    load_stage(1, 32);

    for (int it = 0; it < ITERS; it++) {
        const int s = it % 3;
        CP_WAIT(1);            // oldest outstanding (stage s) complete
        __syncthreads();       // all warps done computing stage (it-1)%3 == (it+2)%3
        if (it + 2 < ITERS) load_stage((it + 2) % 3, (it + 2) * 32);

        const uint32_t baseAh = sb + s * STAGE_BYTES;
        const uint32_t baseAl = baseAh + 8192;
        const uint32_t baseBh = baseAh + 16384;
        const uint32_t baseBl = baseAh + 24576;

#pragma unroll
        for (int sub = 0; sub < 2; sub++) {
            uint32_t bf_h[2][4], bf_l[2][4];
#pragma unroll
            for (int ntp = 0; ntp < 2; ntp++) {
                uint32_t off = b_rowterm[ntp] + ((((uint32_t)(2 * sub + b_kbh)) ^ b_xr[ntp]) << 4);
                ldsm4(bf_h[ntp], baseBh + off);
                ldsm4(bf_l[ntp], baseBl + off);
            }
#pragma unroll
            for (int mt = 0; mt < 4; mt++) {
                uint32_t ah[4], al[4];
                uint32_t off = a_rowterm[mt] + ((((uint32_t)(2 * sub + a_kbh)) ^ a_xr[mt]) << 4);
                ldsm4(ah, baseAh + off);
                ldsm4(al, baseAl + off);
#pragma unroll
                for (int nt = 0; nt < 4; nt++) {
                    const uint32_t* bh2 = &bf_h[nt >> 1][(nt & 1) * 2];
                    const uint32_t* bl2 = &bf_l[nt >> 1][(nt & 1) * 2];
                    mma16816(acc[mt][nt], ah, bh2);
                    mma16816(acc[mt][nt], al, bh2);
                    mma16816(acc[mt][nt], ah, bl2);
                }
            }
        }
        __syncthreads();       // computing done before next iter's producer overwrites
    }

    // ---------------- epilogue ----------------
    const int gid = lane >> 2, tig = lane & 3;
    const float* bias = biasAll + (size_t)e * NC;
    if (EPI == 0) {
#pragma unroll
        for (int mt = 0; mt < 4; mt++) {
#pragma unroll
            for (int half = 0; half < 2; half++) {
                int row = m0 + wm + mt * 16 + gid + half * 8;
                __nv_bfloat16* ph = g_hh + ((size_t)e * K_CAP + row) * F_DIM;
                __nv_bfloat16* pl = g_hl + ((size_t)e * K_CAP + row) * F_DIM;
#pragma unroll
                for (int nt = 0; nt < 4; nt++) {
                    int col = n0 + wn + nt * 8 + tig * 2;
                    float v0 = gelu_tanh(acc[mt][nt][half * 2 + 0] + bias[col]);
                    float v1 = gelu_tanh(acc[mt][nt][half * 2 + 1] + bias[col + 1]);
                    float h0 = __bfloat162float(__float2bfloat16(v0));
                    float h1 = __bfloat162float(__float2bfloat16(v1));
                    *(uint32_t*)(ph + col) = pack_bf2(v0, v1);
                    *(uint32_t*)(pl + col) = pack_bf2(v0 - h0, v1 - h1);
                }
            }
        }
    } else {
#pragma unroll
        for (int mt = 0; mt < 4; mt++) {
#pragma unroll
            for (int half = 0; half < 2; half++) {
                int row = m0 + wm + mt * 16 + gid + half * 8;
                const int tok = g_routes[e * K_CAP + row];
                const float scale = g_vals[e * K_CAP + row];
                float* orow = outFinal + (size_t)tok * D_DIM;
#pragma unroll
                for (int nt = 0; nt < 4; nt++) {
                    int col = n0 + wn + nt * 8 + tig * 2;
                    float v0 = (acc[mt][nt][half * 2 + 0] + bias[col]) * scale;
                    float v1 = (acc[mt][nt][half * 2 + 1] + bias[col + 1]) * scale;
                    atomicAdd(&orow[col], v0);
                    atomicAdd(&orow[col + 1], v1);
                }
            }
        }
    }
}

extern "C" void kernel_launch(void* const* d_in, const int* in_sizes, int n_in,
                              void* d_out, int out_size) {
    const float* x  = (const float*)d_in[0];
    const float* Ws = (const float*)d_in[1];
    const float* bs = (const float*)d_in[2];
    const float* W1 = (const float*)d_in[3];
    const float* b1 = (const float*)d_in[4];
    const float* W2 = (const float*)d_in[5];
    const float* b2 = (const float*)d_in[6];
    float* out = (float*)d_out;

    cudaFuncSetAttribute(moe_mma<0>, cudaFuncAttributeMaxDynamicSharedMemorySize, SMEM_BYTES);
    cudaFuncSetAttribute(moe_mma<1>, cudaFuncAttributeMaxDynamicSharedMemorySize, SMEM_BYTES);

    zero_out_kernel<<<(N_TOK * D_DIM) / (256 * 4), 256>>>((float4*)out);
    gating_kernel<<<N_TOK / 8, dim3(32, 8)>>>(x, Ws, bs);
    topk_kernel<<<E_NUM, 512>>>();
    gather_split_kernel<<<E_NUM * K_CAP, 256>>>(x);
    split_w<0><<<dim3(F_DIM / 32, D_DIM / 32, E_NUM), dim3(32, 8)>>>(W1, D_DIM, F_DIM);
    split_w<1><<<dim3(D_DIM / 32, F_DIM / 32, E_NUM), dim3(32, 8)>>>(W2, F_DIM, D_DIM);
    moe_mma<0><<<dim3(F_DIM / 128, K_CAP / 128, E_NUM), 256, SMEM_BYTES>>>(b1, nullptr);
    moe_mma<1><<<dim3(D_DIM / 128, K_CAP / 128, E_NUM), 256, SMEM_BYTES>>>(b2, out);
}

// round 7
// speedup vs baseline: 3.0486x; 1.2739x over previous
#include <cuda_runtime.h>
#include <cuda_fp16.h>
#include <math.h>
#include <stdint.h>

#define N_TOK 4096
#define D_DIM 1024
#define E_NUM 8
#define F_DIM 4096
#define K_CAP 512

// -------- persistent scratch (device globals; no allocations allowed) --------
__device__ float g_probT[E_NUM * N_TOK];
__device__ int   g_routes[E_NUM * K_CAP];
__device__ float g_vals[E_NUM * K_CAP];
__device__ __align__(16) __half g_x16[(size_t)E_NUM * K_CAP * D_DIM];
__device__ __align__(16) __half g_h16[(size_t)E_NUM * K_CAP * F_DIM];
__device__ __align__(16) __half g_w1h[(size_t)E_NUM * F_DIM * D_DIM];
__device__ __align__(16) __half g_w1l[(size_t)E_NUM * F_DIM * D_DIM];
__device__ __align__(16) __half g_w2h[(size_t)E_NUM * D_DIM * F_DIM];
__device__ __align__(16) __half g_w2l[(size_t)E_NUM * D_DIM * F_DIM];

// ---------------- helpers ----------------
__device__ __forceinline__ uint32_t smem_u32(const void* p) {
    uint32_t a;
    asm("{ .reg .u64 t; cvta.to.shared.u64 t, %1; cvt.u32.u64 %0, t; }" : "=r"(a) : "l"(p));
    return a;
}
#define CP16(dst, src) \
    asm volatile("cp.async.cg.shared.global [%0], [%1], 16;" :: "r"(dst), "l"(src))
#define CP_COMMIT() asm volatile("cp.async.commit_group;" ::: "memory")
#define CP_WAIT(n)  asm volatile("cp.async.wait_group %0;" :: "n"(n) : "memory")

__device__ __forceinline__ void mma16816(float* c, const uint32_t* a, const uint32_t* b) {
    asm volatile(
        "mma.sync.aligned.m16n8k16.row.col.f32.f16.f16.f32 "
        "{%0,%1,%2,%3}, {%4,%5,%6,%7}, {%8,%9}, {%0,%1,%2,%3};"
        : "+f"(c[0]), "+f"(c[1]), "+f"(c[2]), "+f"(c[3])
        : "r"(a[0]), "r"(a[1]), "r"(a[2]), "r"(a[3]), "r"(b[0]), "r"(b[1]));
}
__device__ __forceinline__ void ldsm4(uint32_t* d, uint32_t addr) {
    asm volatile("ldmatrix.sync.aligned.m8n8.x4.shared.b16 {%0,%1,%2,%3}, [%4];"
                 : "=r"(d[0]), "=r"(d[1]), "=r"(d[2]), "=r"(d[3]) : "r"(addr));
}
__device__ __forceinline__ float gelu_tanh(float v) {
    float u = 0.7978845608028654f * (v + 0.044715f * v * v * v);
    float t;
    asm("tanh.approx.f32 %0, %1;" : "=f"(t) : "f"(u));
    return 0.5f * v * (1.0f + t);
}
__device__ __forceinline__ uint32_t pack_h2(float a, float b) {
    __half2 t = __floats2half2_rn(a, b);
    return *(uint32_t*)&t;
}

// ---------------- zero output ----------------
__global__ void zero_out_kernel(float4* __restrict__ out) {
    out[blockIdx.x * blockDim.x + threadIdx.x] = make_float4(0.f, 0.f, 0.f, 0.f);
}

// ---------------- gating ----------------
__global__ void gating_kernel(const float* __restrict__ x,
                              const float* __restrict__ Ws,
                              const float* __restrict__ bs) {
    int t = blockIdx.x * 8 + threadIdx.y;
    int lane = threadIdx.x;
    const float* xr = x + (size_t)t * D_DIM;
    float acc[E_NUM];
#pragma unroll
    for (int e = 0; e < E_NUM; e++) acc[e] = 0.f;
    for (int i = lane; i < D_DIM; i += 32) {
        float xi = xr[i];
        const float* w = Ws + (size_t)i * E_NUM;
#pragma unroll
        for (int e = 0; e < E_NUM; e++) acc[e] += xi * w[e];
    }
#pragma unroll
    for (int e = 0; e < E_NUM; e++)
#pragma unroll
        for (int off = 16; off > 0; off >>= 1)
            acc[e] += __shfl_xor_sync(0xFFFFFFFFu, acc[e], off);
    if (lane == 0) {
        float mx = -1e30f;
#pragma unroll
        for (int e = 0; e < E_NUM; e++) { acc[e] += bs[e]; mx = fmaxf(mx, acc[e]); }
        float s = 0.f;
#pragma unroll
        for (int e = 0; e < E_NUM; e++) { acc[e] = __expf(acc[e] - mx); s += acc[e]; }
        float inv = 1.f / s;
#pragma unroll
        for (int e = 0; e < E_NUM; e++) g_probT[e * N_TOK + t] = acc[e] * inv;
    }
}

// ---------------- per-expert top-k (bitonic) ----------------
__global__ void topk_kernel() {
    __shared__ unsigned long long keys[N_TOK];
    const int e = blockIdx.x;
    const int tid = threadIdx.x;
    for (int i = tid; i < N_TOK; i += 512) {
        unsigned vb = __float_as_uint(g_probT[e * N_TOK + i]);
        keys[i] = ((unsigned long long)vb << 32) | (unsigned)(0xFFFFFFFFu - (unsigned)i);
    }
    __syncthreads();
    for (int k = 2; k <= N_TOK; k <<= 1) {
        for (int j = k >> 1; j > 0; j >>= 1) {
            for (int i = tid; i < N_TOK; i += 512) {
                int ixj = i ^ j;
                if (ixj > i) {
                    unsigned long long a = keys[i], b = keys[ixj];
                    bool up = ((i & k) == 0);
                    if (up ? (a > b) : (a < b)) { keys[i] = b; keys[ixj] = a; }
                }
            }
            __syncthreads();
        }
    }
    for (int i = tid; i < K_CAP; i += 512) {
        unsigned long long kk = keys[N_TOK - K_CAP + i];
        g_vals[e * K_CAP + i]   = __uint_as_float((unsigned)(kk >> 32));
        g_routes[e * K_CAP + i] = (int)(0xFFFFFFFFu - (unsigned)(kk & 0xFFFFFFFFu));
    }
}

// ---------------- gather -> fp16 ----------------
__global__ void gather_kernel(const float* __restrict__ x) {
    int row = blockIdx.x;
    int tok = g_routes[row];
    const float4* src = (const float4*)(x + (size_t)tok * D_DIM);
    float4 v = src[threadIdx.x];
    uint2 h = make_uint2(pack_h2(v.x, v.y), pack_h2(v.z, v.w));
    ((uint2*)(g_x16 + (size_t)row * D_DIM))[threadIdx.x] = h;
}

// ---------------- weight transpose + fp16 hi/lo split ----------------
template <int W>
__global__ void split_w(const float* __restrict__ src, int R, int C) {
    __shared__ float t[32][33];
    __half* dh = W ? g_w2h : g_w1h;
    __half* dl = W ? g_w2l : g_w1l;
    size_t mat = (size_t)blockIdx.z * R * C;
    int c0 = blockIdx.x * 32, r0 = blockIdx.y * 32;
#pragma unroll
    for (int j = threadIdx.y; j < 32; j += 8)
        t[j][threadIdx.x] = src[mat + (size_t)(r0 + j) * C + c0 + threadIdx.x];
    __syncthreads();
#pragma unroll
    for (int j = threadIdx.y; j < 32; j += 8) {
        float v = t[threadIdx.x][j];
        __half h = __float2half_rn(v);
        size_t o = mat + (size_t)(c0 + j) * R + r0 + threadIdx.x;
        dh[o] = h;
        dl[o] = __float2half_rn(v - __half2float(h));
    }
}

// ---------------- fp16 2-pass HMMA grouped GEMM ----------------
// CTA tile 128x128, BK=32, 4-stage cp.async ring (wait_group 2), occupancy 2.
// D = A @ Wh + A @ Wl   (A single fp16, weights split; fp32 accum)
#define STAGE_BYTES 24576     // A 8K | Bh 8K | Bl 8K
#define NSTAGES 4
#define SMEM_BYTES (NSTAGES * STAGE_BYTES)

template <int EPI>
__global__ __launch_bounds__(256, 2)
void moe_mma(const float* __restrict__ biasAll, float* __restrict__ outFinal) {
    constexpr int K  = EPI ? F_DIM : D_DIM;
    constexpr int NC = EPI ? D_DIM : F_DIM;
    constexpr int ITERS = K / 32;

    extern __shared__ char sm[];
    const uint32_t sb = smem_u32(sm);

    const int tid = threadIdx.x, wid = tid >> 5, lane = tid & 31;
    const int e = blockIdx.z, m0 = blockIdx.y * 128, n0 = blockIdx.x * 128;
    const int wm = (wid & 1) * 64, wn = (wid >> 1) * 32;

    const __half* Ag  = (EPI ? g_h16 : g_x16) + (size_t)e * K_CAP * K;
    const __half* Bgh = (EPI ? g_w2h : g_w1h) + (size_t)e * (size_t)NC * K;
    const __half* Bgl = (EPI ? g_w2l : g_w1l) + (size_t)e * (size_t)NC * K;

    // ldmatrix per-lane address precomputation (64B-row swizzled layout)
    const int mi = lane >> 3, j = lane & 7;
    uint32_t a_rowterm[4], a_xr[4];
    const int a_kbh = mi >> 1;
#pragma unroll
    for (int mt = 0; mt < 4; mt++) {
        int row = wm + mt * 16 + ((mi & 1) << 3) + j;
        a_rowterm[mt] = row * 64;
        a_xr[mt] = (row >> 1) & 3;
    }
    uint32_t b_rowterm[2], b_xr[2];
    const int b_kbh = mi & 1;
#pragma unroll
    for (int ntp = 0; ntp < 2; ntp++) {
        int row = wn + ntp * 16 + ((mi >> 1) << 3) + j;
        b_rowterm[ntp] = row * 64;
        b_xr[ntp] = (row >> 1) & 3;
    }

    float acc[4][4][4];
#pragma unroll
    for (int i = 0; i < 4; i++)
#pragma unroll
        for (int jj = 0; jj < 4; jj++)
#pragma unroll
            for (int q = 0; q < 4; q++) acc[i][jj][q] = 0.f;

    // producer: 6 x 16B per thread per stage (A:2, Bh:2, Bl:2)
    auto load_stage = [&](int stage, int k0) {
        const uint32_t base = sb + stage * STAGE_BYTES;
#pragma unroll
        for (int jj = 0; jj < 2; jj++) {
            int cid = tid + jj * 256;
            int row = cid >> 2, kb = cid & 3;
            int pk = kb ^ ((row >> 1) & 3);
            uint32_t doff = row * 64 + pk * 16;
            size_t aoff = (size_t)(m0 + row) * K + k0 + kb * 8;
            size_t boff = (size_t)(n0 + row) * K + k0 + kb * 8;
            CP16(base + doff,         Ag + aoff);
            CP16(base + 8192 + doff,  Bgh + boff);
            CP16(base + 16384 + doff, Bgl + boff);
        }
        CP_COMMIT();
    };

    load_stage(0, 0);
    load_stage(1, 32);
    load_stage(2, 64);

    for (int it = 0; it < ITERS; it++) {
        const int s = it % NSTAGES;
        CP_WAIT(2);
        __syncthreads();
        if (it + 3 < ITERS) load_stage((it + 3) % NSTAGES, (it + 3) * 32);

        const uint32_t baseA  = sb + s * STAGE_BYTES;
        const uint32_t baseBh = baseA + 8192;
        const uint32_t baseBl = baseA + 16384;

#pragma unroll
        for (int sub = 0; sub < 2; sub++) {
            uint32_t bf_h[2][4], bf_l[2][4];
#pragma unroll
            for (int ntp = 0; ntp < 2; ntp++) {
                uint32_t off = b_rowterm[ntp] + ((((uint32_t)(2 * sub + b_kbh)) ^ b_xr[ntp]) << 4);
                ldsm4(bf_h[ntp], baseBh + off);
                ldsm4(bf_l[ntp], baseBl + off);
            }
#pragma unroll
            for (int mt = 0; mt < 4; mt++) {
                uint32_t ah[4];
                uint32_t off = a_rowterm[mt] + ((((uint32_t)(2 * sub + a_kbh)) ^ a_xr[mt]) << 4);
                ldsm4(ah, baseA + off);
#pragma unroll
                for (int nt = 0; nt < 4; nt++) {
                    const uint32_t* bh2 = &bf_h[nt >> 1][(nt & 1) * 2];
                    const uint32_t* bl2 = &bf_l[nt >> 1][(nt & 1) * 2];
                    mma16816(acc[mt][nt], ah, bh2);
                    mma16816(acc[mt][nt], ah, bl2);
                }
            }
        }
        __syncthreads();
    }

    // ---------------- epilogue ----------------
    const int gid = lane >> 2, tig = lane & 3;
    const float* bias = biasAll + (size_t)e * NC;
    if (EPI == 0) {
#pragma unroll
        for (int mt = 0; mt < 4; mt++) {
#pragma unroll
            for (int half = 0; half < 2; half++) {
                int row = m0 + wm + mt * 16 + gid + half * 8;
                __half* ph = g_h16 + ((size_t)e * K_CAP + row) * F_DIM;
#pragma unroll
                for (int nt = 0; nt < 4; nt++) {
                    int col = n0 + wn + nt * 8 + tig * 2;
                    float v0 = gelu_tanh(acc[mt][nt][half * 2 + 0] + bias[col]);
                    float v1 = gelu_tanh(acc[mt][nt][half * 2 + 1] + bias[col + 1]);
                    *(uint32_t*)(ph + col) = pack_h2(v0, v1);
                }
            }
        }
    } else {
#pragma unroll
        for (int mt = 0; mt < 4; mt++) {
#pragma unroll
            for (int half = 0; half < 2; half++) {
                int row = m0 + wm + mt * 16 + gid + half * 8;
                const int tok = g_routes[e * K_CAP + row];
                const float scale = g_vals[e * K_CAP + row];
                float* orow = outFinal + (size_t)tok * D_DIM;
#pragma unroll
                for (int nt = 0; nt < 4; nt++) {
                    int col = n0 + wn + nt * 8 + tig * 2;
                    float v0 = (acc[mt][nt][half * 2 + 0] + bias[col]) * scale;
                    float v1 = (acc[mt][nt][half * 2 + 1] + bias[col + 1]) * scale;
                    atomicAdd(&orow[col], v0);
                    atomicAdd(&orow[col + 1], v1);
                }
            }
        }
    }
}

extern "C" void kernel_launch(void* const* d_in, const int* in_sizes, int n_in,
                              void* d_out, int out_size) {
    const float* x  = (const float*)d_in[0];
    const float* Ws = (const float*)d_in[1];
    const float* bs = (const float*)d_in[2];
    const float* W1 = (const float*)d_in[3];
    const float* b1 = (const float*)d_in[4];
    const float* W2 = (const float*)d_in[5];
    const float* b2 = (const float*)d_in[6];
    float* out = (float*)d_out;

    cudaFuncSetAttribute(moe_mma<0>, cudaFuncAttributeMaxDynamicSharedMemorySize, SMEM_BYTES);
    cudaFuncSetAttribute(moe_mma<1>, cudaFuncAttributeMaxDynamicSharedMemorySize, SMEM_BYTES);

    zero_out_kernel<<<(N_TOK * D_DIM) / (256 * 4), 256>>>((float4*)out);
    gating_kernel<<<N_TOK / 8, dim3(32, 8)>>>(x, Ws, bs);
    topk_kernel<<<E_NUM, 512>>>();
    gather_kernel<<<E_NUM * K_CAP, 256>>>(x);
    split_w<0><<<dim3(F_DIM / 32, D_DIM / 32, E_NUM), dim3(32, 8)>>>(W1, D_DIM, F_DIM);
    split_w<1><<<dim3(D_DIM / 32, F_DIM / 32, E_NUM), dim3(32, 8)>>>(W2, F_DIM, D_DIM);
    moe_mma<0><<<dim3(F_DIM / 128, K_CAP / 128, E_NUM), 256, SMEM_BYTES>>>(b1, nullptr);
    moe_mma<1><<<dim3(D_DIM / 128, K_CAP / 128, E_NUM), 256, SMEM_BYTES>>>(b2, out);
}

// round 10
// speedup vs baseline: 4.2074x; 1.3801x over previous
#include <cuda_runtime.h>
#include <cuda_fp16.h>
#include <math.h>
#include <stdint.h>

#define N_TOK 4096
#define D_DIM 1024
#define E_NUM 8
#define F_DIM 4096
#define K_CAP 512

// -------- persistent scratch (device globals; no allocations allowed) --------
__device__ float g_probT[E_NUM * N_TOK];
__device__ int   g_routes[E_NUM * K_CAP];
__device__ float g_vals[E_NUM * K_CAP];
__device__ __align__(16) __half g_x16[(size_t)E_NUM * K_CAP * D_DIM];
__device__ __align__(16) __half g_h16[(size_t)E_NUM * K_CAP * F_DIM];
__device__ __align__(16) __half g_w1[(size_t)E_NUM * F_DIM * D_DIM];   // W1^T [E][F][D]
__device__ __align__(16) __half g_w2[(size_t)E_NUM * D_DIM * F_DIM];   // W2^T [E][D][F]

// ---------------- helpers ----------------
__device__ __forceinline__ uint32_t smem_u32(const void* p) {
    uint32_t a;
    asm("{ .reg .u64 t; cvta.to.shared.u64 t, %1; cvt.u32.u64 %0, t; }" : "=r"(a) : "l"(p));
    return a;
}
#define CP16(dst, src) \
    asm volatile("cp.async.cg.shared.global [%0], [%1], 16;" :: "r"(dst), "l"(src))
#define CP_COMMIT() asm volatile("cp.async.commit_group;" ::: "memory")
#define CP_WAIT(n)  asm volatile("cp.async.wait_group %0;" :: "n"(n) : "memory")

__device__ __forceinline__ void mma16816(float* c, const uint32_t* a, const uint32_t* b) {
    asm volatile(
        "mma.sync.aligned.m16n8k16.row.col.f32.f16.f16.f32 "
        "{%0,%1,%2,%3}, {%4,%5,%6,%7}, {%8,%9}, {%0,%1,%2,%3};"
        : "+f"(c[0]), "+f"(c[1]), "+f"(c[2]), "+f"(c[3])
        : "r"(a[0]), "r"(a[1]), "r"(a[2]), "r"(a[3]), "r"(b[0]), "r"(b[1]));
}
__device__ __forceinline__ void ldsm4(uint32_t* d, uint32_t addr) {
    asm volatile("ldmatrix.sync.aligned.m8n8.x4.shared.b16 {%0,%1,%2,%3}, [%4];"
                 : "=r"(d[0]), "=r"(d[1]), "=r"(d[2]), "=r"(d[3]) : "r"(addr));
}
__device__ __forceinline__ float gelu_tanh(float v) {
    float u = 0.7978845608028654f * (v + 0.044715f * v * v * v);
    float t;
    asm("tanh.approx.f32 %0, %1;" : "=f"(t) : "f"(u));
    return 0.5f * v * (1.0f + t);
}
__device__ __forceinline__ uint32_t pack_h2(float a, float b) {
    __half2 t = __floats2half2_rn(a, b);
    return *(uint32_t*)&t;
}

// ---------------- zero output ----------------
__global__ void zero_out_kernel(float4* __restrict__ out) {
    out[blockIdx.x * blockDim.x + threadIdx.x] = make_float4(0.f, 0.f, 0.f, 0.f);
}

// ---------------- gating ----------------
__global__ void gating_kernel(const float* __restrict__ x,
                              const float* __restrict__ Ws,
                              const float* __restrict__ bs) {
    int t = blockIdx.x * 8 + threadIdx.y;
    int lane = threadIdx.x;
    const float* xr = x + (size_t)t * D_DIM;
    float acc[E_NUM];
#pragma unroll
    for (int e = 0; e < E_NUM; e++) acc[e] = 0.f;
    for (int i = lane; i < D_DIM; i += 32) {
        float xi = xr[i];
        const float* w = Ws + (size_t)i * E_NUM;
#pragma unroll
        for (int e = 0; e < E_NUM; e++) acc[e] += xi * w[e];
    }
#pragma unroll
    for (int e = 0; e < E_NUM; e++)
#pragma unroll
        for (int off = 16; off > 0; off >>= 1)
            acc[e] += __shfl_xor_sync(0xFFFFFFFFu, acc[e], off);
    if (lane == 0) {
        float mx = -1e30f;
#pragma unroll
        for (int e = 0; e < E_NUM; e++) { acc[e] += bs[e]; mx = fmaxf(mx, acc[e]); }
        float s = 0.f;
#pragma unroll
        for (int e = 0; e < E_NUM; e++) { acc[e] = __expf(acc[e] - mx); s += acc[e]; }
        float inv = 1.f / s;
#pragma unroll
        for (int e = 0; e < E_NUM; e++) g_probT[e * N_TOK + t] = acc[e] * inv;
    }
}

// ---------------- per-expert top-k (bitonic) ----------------
__global__ void topk_kernel() {
    __shared__ unsigned long long keys[N_TOK];
    const int e = blockIdx.x;
    const int tid = threadIdx.x;
    for (int i = tid; i < N_TOK; i += 512) {
        unsigned vb = __float_as_uint(g_probT[e * N_TOK + i]);
        keys[i] = ((unsigned long long)vb << 32) | (unsigned)(0xFFFFFFFFu - (unsigned)i);
    }
    __syncthreads();
    for (int k = 2; k <= N_TOK; k <<= 1) {
        for (int j = k >> 1; j > 0; j >>= 1) {
            for (int i = tid; i < N_TOK; i += 512) {
                int ixj = i ^ j;
                if (ixj > i) {
                    unsigned long long a = keys[i], b = keys[ixj];
                    bool up = ((i & k) == 0);
                    if (up ? (a > b) : (a < b)) { keys[i] = b; keys[ixj] = a; }
                }
            }
            __syncthreads();
        }
    }
    for (int i = tid; i < K_CAP; i += 512) {
        unsigned long long kk = keys[N_TOK - K_CAP + i];
        g_vals[e * K_CAP + i]   = __uint_as_float((unsigned)(kk >> 32));
        g_routes[e * K_CAP + i] = (int)(0xFFFFFFFFu - (unsigned)(kk & 0xFFFFFFFFu));
    }
}

// ---------------- gather -> fp16 ----------------
__global__ void gather_kernel(const float* __restrict__ x) {
    int row = blockIdx.x;
    int tok = g_routes[row];
    const float4* src = (const float4*)(x + (size_t)tok * D_DIM);
    float4 v = src[threadIdx.x];
    uint2 h = make_uint2(pack_h2(v.x, v.y), pack_h2(v.z, v.w));
    ((uint2*)(g_x16 + (size_t)row * D_DIM))[threadIdx.x] = h;
}

// ---------------- weight transpose + fp16 convert ----------------
template <int W>
__global__ void conv_w(const float* __restrict__ src, int R, int C) {
    __shared__ float t[32][33];
    __half* dst = W ? g_w2 : g_w1;
    size_t mat = (size_t)blockIdx.z * R * C;
    int c0 = blockIdx.x * 32, r0 = blockIdx.y * 32;
#pragma unroll
    for (int j = threadIdx.y; j < 32; j += 8)
        t[j][threadIdx.x] = src[mat + (size_t)(r0 + j) * C + c0 + threadIdx.x];
    __syncthreads();
#pragma unroll
    for (int j = threadIdx.y; j < 32; j += 8)
        dst[mat + (size_t)(c0 + j) * R + r0 + threadIdx.x] = __float2half_rn(t[threadIdx.x][j]);
}

// ---------------- fp16 single-pass HMMA grouped GEMM ----------------
// CTA tile 128x128, BK=32, 5-stage cp.async ring (wait_group 3), occupancy 2.
// D = A @ W   (both fp16, fp32 accum)
#define STAGE_BYTES 16384     // A 8K | B 8K
#define NSTAGES 5
#define SMEM_BYTES (NSTAGES * STAGE_BYTES)

template <int EPI>
__global__ __launch_bounds__(256, 2)
void moe_mma(const float* __restrict__ biasAll, float* __restrict__ outFinal) {
    constexpr int K  = EPI ? F_DIM : D_DIM;
    constexpr int NC = EPI ? D_DIM : F_DIM;
    constexpr int ITERS = K / 32;

    extern __shared__ char sm[];
    const uint32_t sb = smem_u32(sm);

    const int tid = threadIdx.x, wid = tid >> 5, lane = tid & 31;
    const int e = blockIdx.z, m0 = blockIdx.y * 128, n0 = blockIdx.x * 128;
    const int wm = (wid & 1) * 64, wn = (wid >> 1) * 32;

    const __half* Ag = (EPI ? g_h16 : g_x16) + (size_t)e * K_CAP * K;
    const __half* Bg = (EPI ? g_w2 : g_w1) + (size_t)e * (size_t)NC * K;

    // ldmatrix per-lane address precomputation (64B-row swizzled layout)
    const int mi = lane >> 3, j = lane & 7;
    uint32_t a_rowterm[4], a_xr[4];
    const int a_kbh = mi >> 1;
#pragma unroll
    for (int mt = 0; mt < 4; mt++) {
        int row = wm + mt * 16 + ((mi & 1) << 3) + j;
        a_rowterm[mt] = row * 64;
        a_xr[mt] = (row >> 1) & 3;
    }
    uint32_t b_rowterm[2], b_xr[2];
    const int b_kbh = mi & 1;
#pragma unroll
    for (int ntp = 0; ntp < 2; ntp++) {
        int row = wn + ntp * 16 + ((mi >> 1) << 3) + j;
        b_rowterm[ntp] = row * 64;
        b_xr[ntp] = (row >> 1) & 3;
    }

    float acc[4][4][4];
#pragma unroll
    for (int i = 0; i < 4; i++)
#pragma unroll
        for (int jj = 0; jj < 4; jj++)
#pragma unroll
            for (int q = 0; q < 4; q++) acc[i][jj][q] = 0.f;

    // producer: 4 x 16B per thread per stage (A:2, B:2)
    auto load_stage = [&](int stage, int k0) {
        const uint32_t base = sb + stage * STAGE_BYTES;
#pragma unroll
        for (int jj = 0; jj < 2; jj++) {
            int cid = tid + jj * 256;
            int row = cid >> 2, kb = cid & 3;
            int pk = kb ^ ((row >> 1) & 3);
            uint32_t doff = row * 64 + pk * 16;
            size_t aoff = (size_t)(m0 + row) * K + k0 + kb * 8;
            size_t boff = (size_t)(n0 + row) * K + k0 + kb * 8;
            CP16(base + doff,        Ag + aoff);
            CP16(base + 8192 + doff, Bg + boff);
        }
        CP_COMMIT();
    };

    load_stage(0, 0);
    load_stage(1, 32);
    load_stage(2, 64);
    load_stage(3, 96);

    for (int it = 0; it < ITERS; it++) {
        const int s = it % NSTAGES;
        CP_WAIT(3);
        __syncthreads();
        if (it + 4 < ITERS) load_stage((it + 4) % NSTAGES, (it + 4) * 32);

        const uint32_t baseA = sb + s * STAGE_BYTES;
        const uint32_t baseB = baseA + 8192;

#pragma unroll
        for (int sub = 0; sub < 2; sub++) {
            uint32_t bf[2][4];
#pragma unroll
            for (int ntp = 0; ntp < 2; ntp++) {
                uint32_t off = b_rowterm[ntp] + ((((uint32_t)(2 * sub + b_kbh)) ^ b_xr[ntp]) << 4);
                ldsm4(bf[ntp], baseB + off);
            }
#pragma unroll
            for (int mt = 0; mt < 4; mt++) {
                uint32_t ah[4];
                uint32_t off = a_rowterm[mt] + ((((uint32_t)(2 * sub + a_kbh)) ^ a_xr[mt]) << 4);
                ldsm4(ah, baseA + off);
#pragma unroll
                for (int nt = 0; nt < 4; nt++) {
                    const uint32_t* b2 = &bf[nt >> 1][(nt & 1) * 2];
                    mma16816(acc[mt][nt], ah, b2);
                }
            }
        }
        __syncthreads();
    }

    // ---------------- epilogue ----------------
    const int gid = lane >> 2, tig = lane & 3;
    const float* bias = biasAll + (size_t)e * NC;
    if (EPI == 0) {
#pragma unroll
        for (int mt = 0; mt < 4; mt++) {
#pragma unroll
            for (int half = 0; half < 2; half++) {
                int row = m0 + wm + mt * 16 + gid + half * 8;
                __half* ph = g_h16 + ((size_t)e * K_CAP + row) * F_DIM;
#pragma unroll
                for (int nt = 0; nt < 4; nt++) {
                    int col = n0 + wn + nt * 8 + tig * 2;
                    float v0 = gelu_tanh(acc[mt][nt][half * 2 + 0] + bias[col]);
                    float v1 = gelu_tanh(acc[mt][nt][half * 2 + 1] + bias[col + 1]);
                    *(uint32_t*)(ph + col) = pack_h2(v0, v1);
                }
            }
        }
    } else {
#pragma unroll
        for (int mt = 0; mt < 4; mt++) {
#pragma unroll
            for (int half = 0; half < 2; half++) {
                int row = m0 + wm + mt * 16 + gid + half * 8;
                const int tok = g_routes[e * K_CAP + row];
                const float scale = g_vals[e * K_CAP + row];
                float* orow = outFinal + (size_t)tok * D_DIM;
#pragma unroll
                for (int nt = 0; nt < 4; nt++) {
                    int col = n0 + wn + nt * 8 + tig * 2;
                    float v0 = (acc[mt][nt][half * 2 + 0] + bias[col]) * scale;
                    float v1 = (acc[mt][nt][half * 2 + 1] + bias[col + 1]) * scale;
                    atomicAdd(&orow[col], v0);
                    atomicAdd(&orow[col + 1], v1);
                }
            }
        }
    }
}

extern "C" void kernel_launch(void* const* d_in, const int* in_sizes, int n_in,
                              void* d_out, int out_size) {
    const float* x  = (const float*)d_in[0];
    const float* Ws = (const float*)d_in[1];
    const float* bs = (const float*)d_in[2];
    const float* W1 = (const float*)d_in[3];
    const float* b1 = (const float*)d_in[4];
    const float* W2 = (const float*)d_in[5];
    const float* b2 = (const float*)d_in[6];
    float* out = (float*)d_out;

    cudaFuncSetAttribute(moe_mma<0>, cudaFuncAttributeMaxDynamicSharedMemorySize, SMEM_BYTES);
    cudaFuncSetAttribute(moe_mma<1>, cudaFuncAttributeMaxDynamicSharedMemorySize, SMEM_BYTES);

    zero_out_kernel<<<(N_TOK * D_DIM) / (256 * 4), 256>>>((float4*)out);
    gating_kernel<<<N_TOK / 8, dim3(32, 8)>>>(x, Ws, bs);
    topk_kernel<<<E_NUM, 512>>>();
    gather_kernel<<<E_NUM * K_CAP, 256>>>(x);
    conv_w<0><<<dim3(F_DIM / 32, D_DIM / 32, E_NUM), dim3(32, 8)>>>(W1, D_DIM, F_DIM);
    conv_w<1><<<dim3(D_DIM / 32, F_DIM / 32, E_NUM), dim3(32, 8)>>>(W2, F_DIM, D_DIM);
    moe_mma<0><<<dim3(F_DIM / 128, K_CAP / 128, E_NUM), 256, SMEM_BYTES>>>(b1, nullptr);
    moe_mma<1><<<dim3(D_DIM / 128, K_CAP / 128, E_NUM), 256, SMEM_BYTES>>>(b2, out);
}

// round 11
// speedup vs baseline: 5.2773x; 1.2543x over previous
#include <cuda_runtime.h>
#include <cuda_fp16.h>
#include <math.h>
#include <stdint.h>

#define N_TOK 4096
#define D_DIM 1024
#define E_NUM 8
#define F_DIM 4096
#define K_CAP 512

// -------- persistent scratch (device globals; no allocations allowed) --------
__device__ float g_probT[E_NUM * N_TOK];
__device__ int   g_routes[E_NUM * K_CAP];
__device__ float g_vals[E_NUM * K_CAP];
__device__ __align__(16) __half g_x16[(size_t)E_NUM * K_CAP * D_DIM];
__device__ __align__(16) __half g_h16[(size_t)E_NUM * K_CAP * F_DIM];
__device__ __align__(16) __half g_w1[(size_t)E_NUM * F_DIM * D_DIM];   // W1^T [E][F][D]
__device__ __align__(16) __half g_w2[(size_t)E_NUM * D_DIM * F_DIM];   // W2^T [E][D][F]

// ---------------- helpers ----------------
__device__ __forceinline__ uint32_t smem_u32(const void* p) {
    uint32_t a;
    asm("{ .reg .u64 t; cvta.to.shared.u64 t, %1; cvt.u32.u64 %0, t; }" : "=r"(a) : "l"(p));
    return a;
}
#define CP16(dst, src) \
    asm volatile("cp.async.cg.shared.global [%0], [%1], 16;" :: "r"(dst), "l"(src))
#define CP_COMMIT() asm volatile("cp.async.commit_group;" ::: "memory")
#define CP_WAIT(n)  asm volatile("cp.async.wait_group %0;" :: "n"(n) : "memory")

__device__ __forceinline__ void mma16816(float* c, const uint32_t* a, const uint32_t* b) {
    asm volatile(
        "mma.sync.aligned.m16n8k16.row.col.f32.f16.f16.f32 "
        "{%0,%1,%2,%3}, {%4,%5,%6,%7}, {%8,%9}, {%0,%1,%2,%3};"
        : "+f"(c[0]), "+f"(c[1]), "+f"(c[2]), "+f"(c[3])
        : "r"(a[0]), "r"(a[1]), "r"(a[2]), "r"(a[3]), "r"(b[0]), "r"(b[1]));
}
__device__ __forceinline__ void ldsm4(uint32_t* d, uint32_t addr) {
    asm volatile("ldmatrix.sync.aligned.m8n8.x4.shared.b16 {%0,%1,%2,%3}, [%4];"
                 : "=r"(d[0]), "=r"(d[1]), "=r"(d[2]), "=r"(d[3]) : "r"(addr));
}
__device__ __forceinline__ float gelu_tanh(float v) {
    float u = 0.7978845608028654f * (v + 0.044715f * v * v * v);
    float t;
    asm("tanh.approx.f32 %0, %1;" : "=f"(t) : "f"(u));
    return 0.5f * v * (1.0f + t);
}
__device__ __forceinline__ uint32_t pack_h2(float a, float b) {
    __half2 t = __floats2half2_rn(a, b);
    return *(uint32_t*)&t;
}

// ============ phase 1: gating (blocks 0..511) || zero_out (blocks 512..4607) ============
__global__ void gate_zero_kernel(const float* __restrict__ x,
                                 const float* __restrict__ Ws,
                                 const float* __restrict__ bs,
                                 float4* __restrict__ out) {
    const int tid = threadIdx.x;
    if (blockIdx.x >= 512) {
        out[(blockIdx.x - 512) * 256 + tid] = make_float4(0.f, 0.f, 0.f, 0.f);
        return;
    }
    const int lane = tid & 31, ty = tid >> 5;
    int t = blockIdx.x * 8 + ty;
    const float* xr = x + (size_t)t * D_DIM;
    float acc[E_NUM];
#pragma unroll
    for (int e = 0; e < E_NUM; e++) acc[e] = 0.f;
    for (int i = lane; i < D_DIM; i += 32) {
        float xi = xr[i];
        const float* w = Ws + (size_t)i * E_NUM;
#pragma unroll
        for (int e = 0; e < E_NUM; e++) acc[e] += xi * w[e];
    }
#pragma unroll
    for (int e = 0; e < E_NUM; e++)
#pragma unroll
        for (int off = 16; off > 0; off >>= 1)
            acc[e] += __shfl_xor_sync(0xFFFFFFFFu, acc[e], off);
    if (lane == 0) {
        float mx = -1e30f;
#pragma unroll
        for (int e = 0; e < E_NUM; e++) { acc[e] += bs[e]; mx = fmaxf(mx, acc[e]); }
        float s = 0.f;
#pragma unroll
        for (int e = 0; e < E_NUM; e++) { acc[e] = __expf(acc[e] - mx); s += acc[e]; }
        float inv = 1.f / s;
#pragma unroll
        for (int e = 0; e < E_NUM; e++) g_probT[e * N_TOK + t] = acc[e] * inv;
    }
}

// ============ phase 2: topk (blocks 0..7) || weight transpose+convert (rest) ============
// 512 threads/block. Conv blocks handle 2 32x32 tiles each (one per 256-thread half).
// W1 tiles: 0..32767  (R=1024=D rows, C=4096=F cols; dst g_w1 [F][D])
// W2 tiles: 32768..65535 (R=4096, C=1024; dst g_w2 [D][F])
#define CONV_BLOCKS ((32768 + 32768) / 2)

__global__ void prep_kernel(const float* __restrict__ W1, const float* __restrict__ W2) {
    __shared__ unsigned long long keys[N_TOK];            // topk blocks
    __shared__ float tt[2][32][33];                       // conv blocks

    const int tid = threadIdx.x;
    if (blockIdx.x < 8) {
        // ---- top-k bitonic sort ----
        const int e = blockIdx.x;
        for (int i = tid; i < N_TOK; i += 512) {
            unsigned vb = __float_as_uint(g_probT[e * N_TOK + i]);
            keys[i] = ((unsigned long long)vb << 32) | (unsigned)(0xFFFFFFFFu - (unsigned)i);
        }
        __syncthreads();
        for (int k = 2; k <= N_TOK; k <<= 1) {
            for (int j = k >> 1; j > 0; j >>= 1) {
                for (int i = tid; i < N_TOK; i += 512) {
                    int ixj = i ^ j;
                    if (ixj > i) {
                        unsigned long long a = keys[i], b = keys[ixj];
                        bool up = ((i & k) == 0);
                        if (up ? (a > b) : (a < b)) { keys[i] = b; keys[ixj] = a; }
                    }
                }
                __syncthreads();
            }
        }
        for (int i = tid; i < K_CAP; i += 512) {
            unsigned long long kk = keys[N_TOK - K_CAP + i];
            g_vals[e * K_CAP + i]   = __uint_as_float((unsigned)(kk >> 32));
            g_routes[e * K_CAP + i] = (int)(0xFFFFFFFFu - (unsigned)(kk & 0xFFFFFFFFu));
        }
        return;
    }

    // ---- conv tile: sub-half of the block handles one 32x32 tile ----
    const int sub = tid >> 8;            // 0 or 1
    const int t8 = tid & 255;
    const int tx = t8 & 31, ty = t8 >> 5;
    const int tile = (blockIdx.x - 8) * 2 + sub;

    const float* src;
    __half* dst;
    int R, C;
    int ltile;
    if (tile < 32768) {                  // W1
        ltile = tile;
        src = W1; dst = g_w1; R = D_DIM; C = F_DIM;
    } else {                             // W2
        ltile = tile - 32768;
        src = W2; dst = g_w2; R = F_DIM; C = D_DIM;
    }
    const int e = ltile >> 12;           // 4096 tiles per expert (either matrix)
    const int rem = ltile & 4095;
    const int ctiles = C >> 5;
    const int c0 = (rem % ctiles) << 5;
    const int r0 = (rem / ctiles) << 5;
    const size_t mat = (size_t)e * D_DIM * F_DIM;

#pragma unroll
    for (int j = ty; j < 32; j += 8)
        tt[sub][j][tx] = src[mat + (size_t)(r0 + j) * C + c0 + tx];
    __syncthreads();
#pragma unroll
    for (int j = ty; j < 32; j += 8)
        dst[mat + (size_t)(c0 + j) * R + r0 + tx] = __float2half_rn(tt[sub][tx][j]);
}

// ---------------- gather -> fp16 ----------------
__global__ void gather_kernel(const float* __restrict__ x) {
    int row = blockIdx.x;
    int tok = g_routes[row];
    const float4* src = (const float4*)(x + (size_t)tok * D_DIM);
    float4 v = src[threadIdx.x];
    uint2 h = make_uint2(pack_h2(v.x, v.y), pack_h2(v.z, v.w));
    ((uint2*)(g_x16 + (size_t)row * D_DIM))[threadIdx.x] = h;
}

// ---------------- fp16 single-pass HMMA grouped GEMM ----------------
// CTA tile 128x128, BK=32, 5-stage cp.async ring (wait_group 3), occupancy 2.
#define STAGE_BYTES 16384     // A 8K | B 8K
#define NSTAGES 5
#define SMEM_BYTES (NSTAGES * STAGE_BYTES)

template <int EPI>
__global__ __launch_bounds__(256, 2)
void moe_mma(const float* __restrict__ biasAll, float* __restrict__ outFinal) {
    constexpr int K  = EPI ? F_DIM : D_DIM;
    constexpr int NC = EPI ? D_DIM : F_DIM;
    constexpr int ITERS = K / 32;

    extern __shared__ char sm[];
    const uint32_t sb = smem_u32(sm);

    const int tid = threadIdx.x, wid = tid >> 5, lane = tid & 31;
    const int e = blockIdx.z, m0 = blockIdx.y * 128, n0 = blockIdx.x * 128;
    const int wm = (wid & 1) * 64, wn = (wid >> 1) * 32;

    const __half* Ag = (EPI ? g_h16 : g_x16) + (size_t)e * K_CAP * K;
    const __half* Bg = (EPI ? g_w2 : g_w1) + (size_t)e * (size_t)NC * K;

    const int mi = lane >> 3, j = lane & 7;
    uint32_t a_rowterm[4], a_xr[4];
    const int a_kbh = mi >> 1;
#pragma unroll
    for (int mt = 0; mt < 4; mt++) {
        int row = wm + mt * 16 + ((mi & 1) << 3) + j;
        a_rowterm[mt] = row * 64;
        a_xr[mt] = (row >> 1) & 3;
    }
    uint32_t b_rowterm[2], b_xr[2];
    const int b_kbh = mi & 1;
#pragma unroll
    for (int ntp = 0; ntp < 2; ntp++) {
        int row = wn + ntp * 16 + ((mi >> 1) << 3) + j;
        b_rowterm[ntp] = row * 64;
        b_xr[ntp] = (row >> 1) & 3;
    }

    float acc[4][4][4];
#pragma unroll
    for (int i = 0; i < 4; i++)
#pragma unroll
        for (int jj = 0; jj < 4; jj++)
#pragma unroll
            for (int q = 0; q < 4; q++) acc[i][jj][q] = 0.f;

    auto load_stage = [&](int stage, int k0) {
        const uint32_t base = sb + stage * STAGE_BYTES;
#pragma unroll
        for (int jj = 0; jj < 2; jj++) {
            int cid = tid + jj * 256;
            int row = cid >> 2, kb = cid & 3;
            int pk = kb ^ ((row >> 1) & 3);
            uint32_t doff = row * 64 + pk * 16;
            size_t aoff = (size_t)(m0 + row) * K + k0 + kb * 8;
            size_t boff = (size_t)(n0 + row) * K + k0 + kb * 8;
            CP16(base + doff,        Ag + aoff);
            CP16(base + 8192 + doff, Bg + boff);
        }
        CP_COMMIT();
    };

    load_stage(0, 0);
    load_stage(1, 32);
    load_stage(2, 64);
    load_stage(3, 96);

    for (int it = 0; it < ITERS; it++) {
        const int s = it % NSTAGES;
        CP_WAIT(3);
        __syncthreads();
        if (it + 4 < ITERS) load_stage((it + 4) % NSTAGES, (it + 4) * 32);

        const uint32_t baseA = sb + s * STAGE_BYTES;
        const uint32_t baseB = baseA + 8192;

#pragma unroll
        for (int sub = 0; sub < 2; sub++) {
            uint32_t bf[2][4];
#pragma unroll
            for (int ntp = 0; ntp < 2; ntp++) {
                uint32_t off = b_rowterm[ntp] + ((((uint32_t)(2 * sub + b_kbh)) ^ b_xr[ntp]) << 4);
                ldsm4(bf[ntp], baseB + off);
            }
#pragma unroll
            for (int mt = 0; mt < 4; mt++) {
                uint32_t ah[4];
                uint32_t off = a_rowterm[mt] + ((((uint32_t)(2 * sub + a_kbh)) ^ a_xr[mt]) << 4);
                ldsm4(ah, baseA + off);
#pragma unroll
                for (int nt = 0; nt < 4; nt++) {
                    const uint32_t* b2 = &bf[nt >> 1][(nt & 1) * 2];
                    mma16816(acc[mt][nt], ah, b2);
                }
            }
        }
        __syncthreads();
    }

    // ---------------- epilogue ----------------
    const int gid = lane >> 2, tig = lane & 3;
    const float* bias = biasAll + (size_t)e * NC;
    if (EPI == 0) {
#pragma unroll
        for (int mt = 0; mt < 4; mt++) {
#pragma unroll
            for (int half = 0; half < 2; half++) {
                int row = m0 + wm + mt * 16 + gid + half * 8;
                __half* ph = g_h16 + ((size_t)e * K_CAP + row) * F_DIM;
#pragma unroll
                for (int nt = 0; nt < 4; nt++) {
                    int col = n0 + wn + nt * 8 + tig * 2;
                    float v0 = gelu_tanh(acc[mt][nt][half * 2 + 0] + bias[col]);
                    float v1 = gelu_tanh(acc[mt][nt][half * 2 + 1] + bias[col + 1]);
                    *(uint32_t*)(ph + col) = pack_h2(v0, v1);
                }
            }
        }
    } else {
#pragma unroll
        for (int mt = 0; mt < 4; mt++) {
#pragma unroll
            for (int half = 0; half < 2; half++) {
                int row = m0 + wm + mt * 16 + gid + half * 8;
                const int tok = g_routes[e * K_CAP + row];
                const float scale = g_vals[e * K_CAP + row];
                float* orow = outFinal + (size_t)tok * D_DIM;
#pragma unroll
                for (int nt = 0; nt < 4; nt++) {
                    int col = n0 + wn + nt * 8 + tig * 2;
                    float v0 = (acc[mt][nt][half * 2 + 0] + bias[col]) * scale;
                    float v1 = (acc[mt][nt][half * 2 + 1] + bias[col + 1]) * scale;
                    atomicAdd(&orow[col], v0);
                    atomicAdd(&orow[col + 1], v1);
                }
            }
        }
    }
}

extern "C" void kernel_launch(void* const* d_in, const int* in_sizes, int n_in,
                              void* d_out, int out_size) {
    const float* x  = (const float*)d_in[0];
    const float* Ws = (const float*)d_in[1];
    const float* bs = (const float*)d_in[2];
    const float* W1 = (const float*)d_in[3];
    const float* b1 = (const float*)d_in[4];
    const float* W2 = (const float*)d_in[5];
    const float* b2 = (const float*)d_in[6];
    float* out = (float*)d_out;

    cudaFuncSetAttribute(moe_mma<0>, cudaFuncAttributeMaxDynamicSharedMemorySize, SMEM_BYTES);
    cudaFuncSetAttribute(moe_mma<1>, cudaFuncAttributeMaxDynamicSharedMemorySize, SMEM_BYTES);

    // phase 1: gating (512 blocks) || zero output (4096 blocks)
    gate_zero_kernel<<<512 + (N_TOK * D_DIM) / (256 * 4), 256>>>(x, Ws, bs, (float4*)out);
    // phase 2: topk (8 blocks) || both weight transposes (32768 blocks)
    prep_kernel<<<8 + CONV_BLOCKS, 512>>>(W1, W2);
    gather_kernel<<<E_NUM * K_CAP, 256>>>(x);
    moe_mma<0><<<dim3(F_DIM / 128, K_CAP / 128, E_NUM), 256, SMEM_BYTES>>>(b1, nullptr);
    moe_mma<1><<<dim3(D_DIM / 128, K_CAP / 128, E_NUM), 256, SMEM_BYTES>>>(b2, out);
}